// round 11
// baseline (speedup 1.0000x reference)
#include <cuda_runtime.h>
#include <math.h>

// ---------------------------------------------------------------------------
// SimpleVQAutoEncoder forward. k1/k2/k3 bit-exact (XLA-CPU-aligned, decide VQ
// indices); k4/k5 image-only -> re-associated. This round: overhead strip:
// duplicated smem tiles (splat = LDS.64), LDS.128 weight loads, hoisted packs.
// Outputs in d_out (fp32): image | indices | commit_loss
// ---------------------------------------------------------------------------

#define BATCH 64
typedef unsigned long long ull;

__device__ float g_h1[BATCH * 16 * 128 * 128];
__device__ float g_h2[BATCH * 32 * 64 * 64];
__device__ float g_q [BATCH * 32 * 64 * 64];
__device__ float g_h3[BATCH * 16 * 128 * 128];
__device__ float g_partial[1024];

// XLA f32 erf: single rational approximation, clamp to [-4,4]. (exact path)
__device__ __forceinline__ float erf_xla(float x) {
    const float w  = fminf(fmaxf(x, -4.0f), 4.0f);
    const float x2 = __fmul_rn(w, w);
    float p = -2.72614225801306e-10f;
    p = __fadd_rn(__fmul_rn(p, x2),  2.77068142495902e-08f);
    p = __fadd_rn(__fmul_rn(p, x2), -2.10102402082508e-06f);
    p = __fadd_rn(__fmul_rn(p, x2), -5.69250639462346e-05f);
    p = __fadd_rn(__fmul_rn(p, x2), -7.34990630326855e-04f);
    p = __fadd_rn(__fmul_rn(p, x2), -2.95459980854025e-03f);
    p = __fadd_rn(__fmul_rn(p, x2), -1.60960333262415e-02f);
    p = __fmul_rn(w, p);
    float q = -1.45660718464996e-05f;
    q = __fadd_rn(__fmul_rn(q, x2), -2.13374055278905e-04f);
    q = __fadd_rn(__fmul_rn(q, x2), -1.68282697438203e-03f);
    q = __fadd_rn(__fmul_rn(q, x2), -7.37332916720468e-03f);
    q = __fadd_rn(__fmul_rn(q, x2), -1.42647390514189e-02f);
    return __fdiv_rn(p, q);
}

__device__ __forceinline__ float gelu_exact(float v) {
    const float t = __fdiv_rn(v, 1.41421356237309504880f);
    const float e = erf_xla(t);
    return 0.5f * __fmul_rn(v, __fadd_rn(e, 1.0f));
}

// Fast gelu for image-only path (k4).
__device__ __forceinline__ float gelu_fast(float v) {
    const float t = v * 0.70710678118654752440f;
    return 0.5f * v * (1.0f + erf_xla(t));
}

__device__ __forceinline__ ull pk2(float lo, float hi) {
    ull r; asm("mov.b64 %0, {%1, %2};" : "=l"(r) : "f"(lo), "f"(hi)); return r;
}
__device__ __forceinline__ void upk2(ull v, float& lo, float& hi) {
    asm("mov.b64 {%0, %1}, %2;" : "=f"(lo), "=f"(hi) : "l"(v));
}
__device__ __forceinline__ ull fma2(ull a, ull b, ull c) {
    ull r; asm("fma.rn.f32x2 %0, %1, %2, %3;" : "=l"(r) : "l"(a), "l"(b), "l"(c));
    return r;
}

// ---------------------------------------------------------------------------
// K1: conv1 (1->16) + bias-after + maxpool2 + gelu (EXACT chains).
// f32x2 over oc pairs; duplicated input tile -> splat via LDS.64.
// Per-lane chain: acc over j=(ky,kx) sequential == previous scalar order.
// ---------------------------------------------------------------------------
__global__ void k1_conv1_pool_gelu(const float* __restrict__ x,
                                   const float* __restrict__ w1,
                                   const float* __restrict__ b1,
                                   float* __restrict__ h1) {
    __shared__ __align__(16) float xs2[34 * 36 * 2];   // duplicated
    __shared__ __align__(16) float wsT[9 * 16];        // [j][oc]
    __shared__ float bs[16];

    const int b   = blockIdx.z;
    const int px0 = blockIdx.x * 16, py0 = blockIdx.y * 16;
    const int ty = threadIdx.y, tx = threadIdx.x;
    const int t  = ty * 16 + tx;

    if (t < 144) { int j = t >> 4, o = t & 15; wsT[j * 16 + o] = w1[o * 9 + j]; }
    if (t < 16)  bs[t] = b1[t];

    const float* xb = x + (size_t)b * 65536;
    for (int i = t; i < 34 * 34; i += 256) {
        int r = i / 34, c = i % 34;
        int gy = 2 * py0 - 1 + r, gx = 2 * px0 - 1 + c;
        float v = 0.0f;
        if (gy >= 0 && gy < 256 && gx >= 0 && gx < 256) v = xb[gy * 256 + gx];
        const int idx = (r * 36 + c) * 2;
        xs2[idx] = v; xs2[idx + 1] = v;
    }
    __syncthreads();

    ull acc[4][8];
    #pragma unroll
    for (int pos = 0; pos < 4; pos++)
        #pragma unroll
        for (int p = 0; p < 8; p++) acc[pos][p] = 0;

    #pragma unroll
    for (int j = 0; j < 9; j++) {
        const int ky = j / 3, kx = j % 3;
        const float* fbase = xs2 + ((2 * ty + ky) * 36 + (2 * tx + kx)) * 2;
        const ull x00 = *(const ull*)(fbase);
        const ull x01 = *(const ull*)(fbase + 2);
        const ull x10 = *(const ull*)(fbase + 72);
        const ull x11 = *(const ull*)(fbase + 74);
        const ulonglong2* wr = (const ulonglong2*)(wsT + j * 16);
        #pragma unroll
        for (int h = 0; h < 4; h++) {
            const ulonglong2 wv = wr[h];
            acc[0][2*h  ] = fma2(wv.x, x00, acc[0][2*h  ]);
            acc[0][2*h+1] = fma2(wv.y, x00, acc[0][2*h+1]);
            acc[1][2*h  ] = fma2(wv.x, x01, acc[1][2*h  ]);
            acc[1][2*h+1] = fma2(wv.y, x01, acc[1][2*h+1]);
            acc[2][2*h  ] = fma2(wv.x, x10, acc[2][2*h  ]);
            acc[2][2*h+1] = fma2(wv.y, x10, acc[2][2*h+1]);
            acc[3][2*h  ] = fma2(wv.x, x11, acc[3][2*h  ]);
            acc[3][2*h+1] = fma2(wv.y, x11, acc[3][2*h+1]);
        }
    }

    #pragma unroll
    for (int p = 0; p < 8; p++) {
        float a0[4], a1[4];
        #pragma unroll
        for (int pos = 0; pos < 4; pos++) upk2(acc[pos][p], a0[pos], a1[pos]);
        const int oc0 = 2 * p, oc1 = 2 * p + 1;
        const float bb0 = bs[oc0], bb1 = bs[oc1];
        const float m0 = fmaxf(fmaxf(__fadd_rn(a0[0], bb0), __fadd_rn(a0[1], bb0)),
                               fmaxf(__fadd_rn(a0[2], bb0), __fadd_rn(a0[3], bb0)));
        const float m1 = fmaxf(fmaxf(__fadd_rn(a1[0], bb1), __fadd_rn(a1[1], bb1)),
                               fmaxf(__fadd_rn(a1[2], bb1), __fadd_rn(a1[3], bb1)));
        h1[(((size_t)b * 16 + oc0) * 128 + (py0 + ty)) * 128 + (px0 + tx)] = gelu_exact(m0);
        h1[(((size_t)b * 16 + oc1) * 128 + (py0 + ty)) * 128 + (px0 + tx)] = gelu_exact(m1);
    }
}

// ---------------------------------------------------------------------------
// K2: conv2 (16->32), EXACT per-oc chain over (ky,kx,ic) ic-innermost.
// Duplicated input tile (splat = LDS.64), LDS.128 weights.
// dyn smem = (16*18*18*2 + 144*32 + 32)*4 = 60032 B.
// ---------------------------------------------------------------------------
__global__ void k2_conv2_pool(const float* __restrict__ h1,
                              const float* __restrict__ w2,
                              const float* __restrict__ b2,
                              float* __restrict__ h2) {
    extern __shared__ __align__(16) float sm2[];
    float* hs2 = sm2;             // 10368 floats, dup [ic][18][18][2]
    float* wsT = sm2 + 10368;     // 4608 floats, [j][32oc]
    float* bs  = sm2 + 14976;     // 32

    const int b   = blockIdx.z;
    const int px0 = blockIdx.x * 8, py0 = blockIdx.y * 8;
    const int t   = threadIdx.x;

    for (int i = t; i < 4608; i += 256) {
        int o = i & 31, j = i >> 5;
        wsT[j * 32 + o] = w2[o * 144 + j];
    }
    if (t < 32) bs[t] = b2[t];

    const float* hb = h1 + (size_t)b * 16 * 16384;
    for (int i = t; i < 16 * 18 * 18; i += 256) {
        int ic = i / 324, rem = i % 324;
        int r = rem / 18, c = rem % 18;
        int gy = 2 * py0 - 1 + r, gx = 2 * px0 - 1 + c;
        float v = 0.0f;
        if (gy >= 0 && gy < 128 && gx >= 0 && gx < 128) v = hb[ic * 16384 + gy * 128 + gx];
        const int idx = i * 2;
        hs2[idx] = v; hs2[idx + 1] = v;
    }
    __syncthreads();

    const int s  = t & 63, g = t >> 6;
    const int px = s & 7, py = s >> 3;

    ull acc[4][4];
    #pragma unroll
    for (int p = 0; p < 4; p++)
        #pragma unroll
        for (int wv = 0; wv < 4; wv++) acc[p][wv] = 0;

    #pragma unroll
    for (int ky = 0; ky < 3; ky++)
    #pragma unroll
    for (int kx = 0; kx < 3; kx++) {
        for (int ic = 0; ic < 16; ic++) {          // ic innermost (exact order)
            const float* fb = hs2 + ((ic * 18 + 2 * py + ky) * 18 + (2 * px + kx)) * 2;
            const ull s00 = *(const ull*)(fb);
            const ull s01 = *(const ull*)(fb + 2);
            const ull s10 = *(const ull*)(fb + 36);
            const ull s11 = *(const ull*)(fb + 38);
            const int j = ic * 9 + ky * 3 + kx;
            const ulonglong2* wrow = (const ulonglong2*)(wsT + j * 32 + g * 8);
            const ulonglong2 wA = wrow[0], wB = wrow[1];
            acc[0][0] = fma2(wA.x, s00, acc[0][0]);
            acc[0][1] = fma2(wA.x, s01, acc[0][1]);
            acc[0][2] = fma2(wA.x, s10, acc[0][2]);
            acc[0][3] = fma2(wA.x, s11, acc[0][3]);
            acc[1][0] = fma2(wA.y, s00, acc[1][0]);
            acc[1][1] = fma2(wA.y, s01, acc[1][1]);
            acc[1][2] = fma2(wA.y, s10, acc[1][2]);
            acc[1][3] = fma2(wA.y, s11, acc[1][3]);
            acc[2][0] = fma2(wB.x, s00, acc[2][0]);
            acc[2][1] = fma2(wB.x, s01, acc[2][1]);
            acc[2][2] = fma2(wB.x, s10, acc[2][2]);
            acc[2][3] = fma2(wB.x, s11, acc[2][3]);
            acc[3][0] = fma2(wB.y, s00, acc[3][0]);
            acc[3][1] = fma2(wB.y, s01, acc[3][1]);
            acc[3][2] = fma2(wB.y, s10, acc[3][2]);
            acc[3][3] = fma2(wB.y, s11, acc[3][3]);
        }
    }

    #pragma unroll
    for (int p = 0; p < 4; p++) {
        float a0[4], a1[4];
        #pragma unroll
        for (int wv = 0; wv < 4; wv++) upk2(acc[p][wv], a0[wv], a1[wv]);
        const int oc0 = g * 8 + 2 * p, oc1 = oc0 + 1;
        const float bb0 = bs[oc0], bb1 = bs[oc1];
        float m0 = fmaxf(fmaxf(__fadd_rn(a0[0], bb0), __fadd_rn(a0[1], bb0)),
                         fmaxf(__fadd_rn(a0[2], bb0), __fadd_rn(a0[3], bb0)));
        float m1 = fmaxf(fmaxf(__fadd_rn(a1[0], bb1), __fadd_rn(a1[1], bb1)),
                         fmaxf(__fadd_rn(a1[2], bb1), __fadd_rn(a1[3], bb1)));
        h2[(((size_t)b * 32 + oc0) * 64 + (py0 + py)) * 64 + (px0 + px)] = m0;
        h2[(((size_t)b * 32 + oc1) * 64 + (py0 + py)) * 64 + (px0 + px)] = m1;
    }
}

// ---------------------------------------------------------------------------
// K3: VQ (EXACT). 2 vectors/thread; x splats PACKED ONCE (hoisted out of
// k-loop); LDS.128 codebook rows. grid 512, block 256, dyn smem 67584 B.
// ---------------------------------------------------------------------------
__global__ void __launch_bounds__(256, 1)
k3_vq(const float* __restrict__ h2,
      const float* __restrict__ cb,
      float* __restrict__ q,
      float* __restrict__ outF,
      float* __restrict__ partial) {
    extern __shared__ __align__(16) float sm[];
    float* scbT = sm;             // [32][512]
    float* sc2  = sm + 32 * 512;  // [512]
    const int t = threadIdx.x;

    for (int i = t; i < 32 * 512; i += 256) {
        int d = i >> 9, k = i & 511;
        scbT[i] = cb[k * 32 + d];
    }
    for (int k = t; k < 512; k += 256) {
        const float* c = cb + k * 32;
        float s = 0.0f;
        #pragma unroll
        for (int d = 0; d < 32; d++) s = __fadd_rn(s, __fmul_rn(c[d], c[d]));
        sc2[k] = s;
    }
    __syncthreads();

    const int vA = blockIdx.x * 256 + t;        // [0, 131072)
    const int vB = vA + 131072;
    const int bA = vA >> 12, pA = vA & 4095;
    const int bB = vB >> 12, pB = vB & 4095;
    const float* hA = h2 + ((size_t)bA * 32) * 4096 + pA;
    const float* hB = h2 + ((size_t)bB * 32) * 4096 + pB;

    ull xsA[32], xsB[32];
    float x2A = 0.0f, x2B = 0.0f;
    #pragma unroll
    for (int d = 0; d < 32; d++) {
        const float a = hA[(size_t)d * 4096];
        const float b = hB[(size_t)d * 4096];
        x2A = __fadd_rn(x2A, __fmul_rn(a, a));
        x2B = __fadd_rn(x2B, __fmul_rn(b, b));
        xsA[d] = pk2(a, a);
        xsB[d] = pk2(b, b);
    }

    float bestA = 3.4e38f, bestB = 3.4e38f;
    int biA = 0, biB = 0;
    for (int k0 = 0; k0 < 512; k0 += 8) {
        ull aA0 = 0, aA1 = 0, aA2 = 0, aA3 = 0;
        ull aB0 = 0, aB1 = 0, aB2 = 0, aB3 = 0;
        #pragma unroll
        for (int d = 0; d < 32; d++) {
            const ulonglong2* row = (const ulonglong2*)(scbT + d * 512 + k0);
            const ulonglong2 rA = row[0], rB = row[1];
            const ull xa = xsA[d], xb = xsB[d];
            aA0 = fma2(rA.x, xa, aA0); aA1 = fma2(rA.y, xa, aA1);
            aA2 = fma2(rB.x, xa, aA2); aA3 = fma2(rB.y, xa, aA3);
            aB0 = fma2(rA.x, xb, aB0); aB1 = fma2(rA.y, xb, aB1);
            aB2 = fma2(rB.x, xb, aB2); aB3 = fma2(rB.y, xb, aB3);
        }
        float xcA[8], xcB[8];
        upk2(aA0, xcA[0], xcA[1]); upk2(aA1, xcA[2], xcA[3]);
        upk2(aA2, xcA[4], xcA[5]); upk2(aA3, xcA[6], xcA[7]);
        upk2(aB0, xcB[0], xcB[1]); upk2(aB1, xcB[2], xcB[3]);
        upk2(aB2, xcB[4], xcB[5]); upk2(aB3, xcB[6], xcB[7]);
        #pragma unroll
        for (int j = 0; j < 8; j++) {
            const float c2 = sc2[k0 + j];
            const float dA = __fadd_rn(__fsub_rn(x2A, __fmul_rn(2.0f, xcA[j])), c2);
            const float dB = __fadd_rn(__fsub_rn(x2B, __fmul_rn(2.0f, xcB[j])), c2);
            if (dA < bestA) { bestA = dA; biA = k0 + j; }
            if (dB < bestB) { bestB = dB; biB = k0 + j; }
        }
    }

    float err = 0.0f;
    {
        const float* c = cb + biA * 32;
        float* qb = q + ((size_t)bA * 32) * 4096 + pA;
        #pragma unroll
        for (int d = 0; d < 32; d++) {
            float xa, tmp; upk2(xsA[d], xa, tmp);
            const float e = __fsub_rn(c[d], xa);
            err = __fadd_rn(err, __fmul_rn(e, e));
            qb[(size_t)d * 4096] = __fadd_rn(xa, e);
        }
        outF[4194304 + vA] = (float)biA;
    }
    {
        const float* c = cb + biB * 32;
        float* qb = q + ((size_t)bB * 32) * 4096 + pB;
        #pragma unroll
        for (int d = 0; d < 32; d++) {
            float xb, tmp; upk2(xsB[d], xb, tmp);
            const float e = __fsub_rn(c[d], xb);
            err = __fadd_rn(err, __fmul_rn(e, e));
            qb[(size_t)d * 4096] = __fadd_rn(xb, e);
        }
        outF[4194304 + vB] = (float)biB;
    }

    __shared__ float red[256];
    red[t] = err;
    __syncthreads();
    #pragma unroll
    for (int s2 = 128; s2 > 0; s2 >>= 1) {
        if (t < s2) red[t] += red[t + s2];
        __syncthreads();
    }
    if (t == 0) partial[blockIdx.x] = red[0];
}

// ---------------------------------------------------------------------------
// K4: upsample2 + conv3 + bias + gelu, PHASE-DECOMPOSED (image path).
// Duplicated q tile (splat = LDS.64); cw layout [ph][c][tap][oc] -> LDS.128.
// dyn smem = (11520 + 8192 + 16)*4 = 78912 B. grid (4,8,B).
// ---------------------------------------------------------------------------
__global__ void k4_up_conv3_gelu(const float* __restrict__ q,
                                 const float* __restrict__ w3,
                                 const float* __restrict__ b3,
                                 float* __restrict__ h3) {
    extern __shared__ __align__(16) float sm4[];
    float* qs2 = sm4;                // 11520 floats dup tile [32][10][18][2]; temp for w3
    float* cw  = sm4 + 11520;        // 8192: [ph][c][tap][oc16]
    float* bs  = sm4 + 19712;        // 16

    const int b   = blockIdx.z;
    const int ox0 = blockIdx.x * 32, oy0 = blockIdx.y * 16;
    const int t   = threadIdx.x;

    for (int i = t; i < 4608; i += 256) qs2[i] = w3[i];
    if (t < 16) bs[t] = b3[t];
    __syncthreads();

    // combined weights: cw[((ph*32+c)*4+tap)*16+o]
    for (int e = t; e < 8192; e += 256) {
        const int o = e & 15, tap = (e >> 4) & 3, c = (e >> 6) & 31, ph = e >> 11;
        const int tx = tap & 1, ty = tap >> 1, dx = ph & 1, dy = ph >> 1;
        const int ys = dy ? (ty ? 2 : 0) : (ty ? 1 : 0);
        const int yc = dy ? (ty ? 1 : 2) : (ty ? 2 : 1);
        const int xs = dx ? (tx ? 2 : 0) : (tx ? 1 : 0);
        const int xc = dx ? (tx ? 1 : 2) : (tx ? 2 : 1);
        float ssum = 0.0f;
        for (int iy = 0; iy < yc; iy++)
            for (int ix = 0; ix < xc; ix++)
                ssum += qs2[o * 288 + c * 9 + (ys + iy) * 3 + (xs + ix)];
        cw[e] = ssum;
    }
    __syncthreads();

    // duplicated q tile [32][10][18][2], zero-filled OOB
    const int qyb = (oy0 >> 1) - 1, qxb = (ox0 >> 1) - 1;
    const float* qb_ = q + (size_t)b * 131072;
    for (int i = t; i < 5760; i += 256) {
        const int c = i / 180, rem = i % 180, r = rem / 18, cc = rem % 18;
        const int gy = qyb + r, gx = qxb + cc;
        float v = 0.0f;
        if (gy >= 0 && gy < 64 && gx >= 0 && gx < 64) v = qb_[c * 4096 + gy * 64 + gx];
        qs2[i * 2] = v; qs2[i * 2 + 1] = v;
    }
    __syncthreads();

    const int wrp = t >> 5, lane = t & 31;
    const int dx = wrp & 1, dy = (wrp >> 1) & 1, sub = wrp >> 2;
    const int ph = dy * 2 + dx;
    const int idxA = sub * 32 + lane, idxB = idxA + 64;
    const int uxA = idxA & 15, uyA = idxA >> 4;
    const int uxB = idxB & 15, uyB = idxB >> 4;
    const int jxA = uxA + dx, jyA = uyA + dy;
    const int jxB = uxB + dx, jyB = uyB + dy;

    ull A[8], B[8];
    #pragma unroll
    for (int p = 0; p < 8; p++) { A[p] = 0; B[p] = 0; }

    const float* cwp = cw + ph * 2048;
    for (int c = 0; c < 32; c++) {
        const float* fA = qs2 + c * 360 + (jyA * 18 + jxA) * 2;
        const float* fB = qs2 + c * 360 + (jyB * 18 + jxB) * 2;
        const ull sa[4] = { *(const ull*)(fA),      *(const ull*)(fA + 2),
                            *(const ull*)(fA + 36), *(const ull*)(fA + 38) };
        const ull sb[4] = { *(const ull*)(fB),      *(const ull*)(fB + 2),
                            *(const ull*)(fB + 36), *(const ull*)(fB + 38) };
        #pragma unroll
        for (int tap = 0; tap < 4; tap++) {
            const ulonglong2* wr = (const ulonglong2*)(cwp + (c * 4 + tap) * 16);
            #pragma unroll
            for (int h = 0; h < 4; h++) {
                const ulonglong2 wv = wr[h];
                A[2*h  ] = fma2(wv.x, sa[tap], A[2*h  ]);
                A[2*h+1] = fma2(wv.y, sa[tap], A[2*h+1]);
                B[2*h  ] = fma2(wv.x, sb[tap], B[2*h  ]);
                B[2*h+1] = fma2(wv.y, sb[tap], B[2*h+1]);
            }
        }
    }

    const int oxA = ox0 + 2 * uxA + dx, oyA = oy0 + 2 * uyA + dy;
    const int oxB = ox0 + 2 * uxB + dx, oyB = oy0 + 2 * uyB + dy;
    #pragma unroll
    for (int p = 0; p < 8; p++) {
        float a0, a1, c0, c1;
        upk2(A[p], a0, a1);
        upk2(B[p], c0, c1);
        h3[(((size_t)b * 16 + 2 * p + 0) * 128 + oyA) * 128 + oxA] = gelu_fast(a0 + bs[2 * p + 0]);
        h3[(((size_t)b * 16 + 2 * p + 1) * 128 + oyA) * 128 + oxA] = gelu_fast(a1 + bs[2 * p + 1]);
        h3[(((size_t)b * 16 + 2 * p + 0) * 128 + oyB) * 128 + oxB] = gelu_fast(c0 + bs[2 * p + 0]);
        h3[(((size_t)b * 16 + 2 * p + 1) * 128 + oyB) * 128 + oxB] = gelu_fast(c1 + bs[2 * p + 1]);
    }
}

// ---------------------------------------------------------------------------
// K5: upsample2 + conv4 (16->1) + clip, PHASE-DECOMPOSED (image path).
// Tile 32x32 out, 4 px/thread. grid (8,8,B).
// ---------------------------------------------------------------------------
__global__ void k5_up_conv4_clip(const float* __restrict__ h3,
                                 const float* __restrict__ w4,
                                 const float* __restrict__ b4,
                                 float* __restrict__ outF) {
    __shared__ float hs[16 * 18 * 18];
    __shared__ float cw5[256];
    __shared__ float wtmp[144];

    const int b   = blockIdx.z;
    const int ox0 = blockIdx.x * 32, oy0 = blockIdx.y * 32;
    const int t   = threadIdx.x;

    if (t < 144) wtmp[t] = w4[t];
    __syncthreads();

    {
        const int c = t & 15, tap = (t >> 4) & 3, ph = t >> 6;
        const int tx = tap & 1, ty = tap >> 1, dx = ph & 1, dy = ph >> 1;
        const int ys = dy ? (ty ? 2 : 0) : (ty ? 1 : 0);
        const int yc = dy ? (ty ? 1 : 2) : (ty ? 2 : 1);
        const int xs = dx ? (tx ? 2 : 0) : (tx ? 1 : 0);
        const int xc = dx ? (tx ? 1 : 2) : (tx ? 2 : 1);
        float ssum = 0.0f;
        for (int iy = 0; iy < yc; iy++)
            for (int ix = 0; ix < xc; ix++)
                ssum += wtmp[c * 9 + (ys + iy) * 3 + (xs + ix)];
        cw5[t] = ssum;
    }

    const int qyb = (oy0 >> 1) - 1, qxb = (ox0 >> 1) - 1;
    const float* hb = h3 + (size_t)b * 16 * 16384;
    for (int i = t; i < 16 * 324; i += 256) {
        const int c = i / 324, rem = i % 324, r = rem / 18, cc = rem % 18;
        const int gy = qyb + r, gx = qxb + cc;
        float v = 0.0f;
        if (gy >= 0 && gy < 128 && gx >= 0 && gx < 128) v = hb[c * 16384 + gy * 128 + gx];
        hs[c * 324 + r * 18 + cc] = v;
    }
    __syncthreads();

    const int wrp = t >> 5, lane = t & 31;
    const int dx = wrp & 1, dy = (wrp >> 1) & 1, sub = wrp >> 2;
    const float* cwp = cw5 + (dy * 2 + dx) * 64;
    const float bias = b4[0];

    int jx[4], jy[4], ox[4], oy[4];
    #pragma unroll
    for (int i = 0; i < 4; i++) {
        const int idx = sub * 32 + lane + 64 * i;
        const int ux = idx & 15, uy = idx >> 4;
        jx[i] = ux + dx; jy[i] = uy + dy;
        ox[i] = ox0 + 2 * ux + dx; oy[i] = oy0 + 2 * uy + dy;
    }

    float acc[4] = {0.f, 0.f, 0.f, 0.f};
    for (int c = 0; c < 16; c++) {
        const float w00 = cwp[c], w01 = cwp[16 + c], w10 = cwp[32 + c], w11 = cwp[48 + c];
        const float* hc = hs + c * 324;
        #pragma unroll
        for (int i = 0; i < 4; i++) {
            acc[i] = fmaf(hc[jy[i] * 18 + jx[i]],           w00, acc[i]);
            acc[i] = fmaf(hc[jy[i] * 18 + jx[i] + 1],       w01, acc[i]);
            acc[i] = fmaf(hc[(jy[i] + 1) * 18 + jx[i]],     w10, acc[i]);
            acc[i] = fmaf(hc[(jy[i] + 1) * 18 + jx[i] + 1], w11, acc[i]);
        }
    }

    #pragma unroll
    for (int i = 0; i < 4; i++) {
        float a = acc[i] + bias;
        a = fminf(fmaxf(a, -1.0f), 1.0f);
        outF[(size_t)b * 65536 + oy[i] * 256 + ox[i]] = a;
    }
}

// ---------------------------------------------------------------------------
// K6: deterministic final reduction of commit loss (512 partials).
// ---------------------------------------------------------------------------
__global__ void k6_loss(const float* __restrict__ partial, float* __restrict__ outF) {
    __shared__ float red[256];
    const int t = threadIdx.x;
    red[t] = partial[t] + partial[t + 256];
    __syncthreads();
    #pragma unroll
    for (int s2 = 128; s2 > 0; s2 >>= 1) {
        if (t < s2) red[t] += red[t + s2];
        __syncthreads();
    }
    if (t == 0) outF[4194304 + 262144] = red[0] * (1.0f / 8388608.0f);
}

// ---------------------------------------------------------------------------
extern "C" void kernel_launch(void* const* d_in, const int* in_sizes, int n_in,
                              void* d_out, int out_size) {
    const float* x  = (const float*)d_in[0];
    const float* w1 = (const float*)d_in[1];
    const float* b1 = (const float*)d_in[2];
    const float* w2 = (const float*)d_in[3];
    const float* b2 = (const float*)d_in[4];
    const float* cb = (const float*)d_in[5];
    const float* w3 = (const float*)d_in[6];
    const float* b3 = (const float*)d_in[7];
    const float* w4 = (const float*)d_in[8];
    const float* b4 = (const float*)d_in[9];
    float* outF = (float*)d_out;

    float *h1, *h2, *q, *h3, *partial;
    cudaGetSymbolAddress((void**)&h1, g_h1);
    cudaGetSymbolAddress((void**)&h2, g_h2);
    cudaGetSymbolAddress((void**)&q,  g_q);
    cudaGetSymbolAddress((void**)&h3, g_h3);
    cudaGetSymbolAddress((void**)&partial, g_partial);

    cudaFuncSetAttribute(k2_conv2_pool,    cudaFuncAttributeMaxDynamicSharedMemorySize, 60032);
    cudaFuncSetAttribute(k3_vq,            cudaFuncAttributeMaxDynamicSharedMemorySize, 67584);
    cudaFuncSetAttribute(k4_up_conv3_gelu, cudaFuncAttributeMaxDynamicSharedMemorySize, 78912);

    k1_conv1_pool_gelu<<<dim3(8, 8, BATCH), dim3(16, 16)>>>(x, w1, b1, h1);
    k2_conv2_pool<<<dim3(8, 8, BATCH), 256, 60032>>>(h1, w2, b2, h2);
    k3_vq<<<512, 256, 67584>>>(h2, cb, q, outF, partial);
    k4_up_conv3_gelu<<<dim3(4, 8, BATCH), 256, 78912>>>(q, w3, b3, h3);
    k5_up_conv4_clip<<<dim3(8, 8, BATCH), 256>>>(h3, w4, b4, outF);
    k6_loss<<<1, 256>>>(partial, outF);
}

// round 12
// speedup vs baseline: 1.0734x; 1.0734x over previous
#include <cuda_runtime.h>
#include <math.h>

// ---------------------------------------------------------------------------
// SimpleVQAutoEncoder forward. k1/k2/k3 bit-exact (XLA-CPU-aligned, decide VQ
// indices); k4/k5 image-only -> re-associated (phase-decomposed).
// R12 = R9 (873us baseline) + LDS.128 weight loads in k2/k4 (smem-neutral).
// Outputs in d_out (fp32): image | indices | commit_loss
// ---------------------------------------------------------------------------

#define BATCH 64
typedef unsigned long long ull;

__device__ float g_h1[BATCH * 16 * 128 * 128];
__device__ float g_h2[BATCH * 32 * 64 * 64];
__device__ float g_q [BATCH * 32 * 64 * 64];
__device__ float g_h3[BATCH * 16 * 128 * 128];
__device__ float g_partial[1024];

// XLA f32 erf: single rational approximation, clamp to [-4,4]. (exact path)
__device__ __forceinline__ float erf_xla(float x) {
    const float w  = fminf(fmaxf(x, -4.0f), 4.0f);
    const float x2 = __fmul_rn(w, w);
    float p = -2.72614225801306e-10f;
    p = __fadd_rn(__fmul_rn(p, x2),  2.77068142495902e-08f);
    p = __fadd_rn(__fmul_rn(p, x2), -2.10102402082508e-06f);
    p = __fadd_rn(__fmul_rn(p, x2), -5.69250639462346e-05f);
    p = __fadd_rn(__fmul_rn(p, x2), -7.34990630326855e-04f);
    p = __fadd_rn(__fmul_rn(p, x2), -2.95459980854025e-03f);
    p = __fadd_rn(__fmul_rn(p, x2), -1.60960333262415e-02f);
    p = __fmul_rn(w, p);
    float q = -1.45660718464996e-05f;
    q = __fadd_rn(__fmul_rn(q, x2), -2.13374055278905e-04f);
    q = __fadd_rn(__fmul_rn(q, x2), -1.68282697438203e-03f);
    q = __fadd_rn(__fmul_rn(q, x2), -7.37332916720468e-03f);
    q = __fadd_rn(__fmul_rn(q, x2), -1.42647390514189e-02f);
    return __fdiv_rn(p, q);
}

__device__ __forceinline__ float gelu_exact(float v) {
    const float t = __fdiv_rn(v, 1.41421356237309504880f);
    const float e = erf_xla(t);
    return 0.5f * __fmul_rn(v, __fadd_rn(e, 1.0f));
}

// Fast gelu for image-only path (k4).
__device__ __forceinline__ float gelu_fast(float v) {
    const float t = v * 0.70710678118654752440f;
    return 0.5f * v * (1.0f + erf_xla(t));
}

__device__ __forceinline__ ull pk2(float lo, float hi) {
    ull r; asm("mov.b64 %0, {%1, %2};" : "=l"(r) : "f"(lo), "f"(hi)); return r;
}
__device__ __forceinline__ void upk2(ull v, float& lo, float& hi) {
    asm("mov.b64 {%0, %1}, %2;" : "=f"(lo), "=f"(hi) : "l"(v));
}
__device__ __forceinline__ ull fma2(ull a, ull b, ull c) {
    ull r; asm("fma.rn.f32x2 %0, %1, %2, %3;" : "=l"(r) : "l"(a), "l"(b), "l"(c));
    return r;
}

// ---------------------------------------------------------------------------
// K1: conv1 (1->16) + bias-after + maxpool2 + gelu (EXACT). [B,16,128,128]
// ---------------------------------------------------------------------------
__global__ void k1_conv1_pool_gelu(const float* __restrict__ x,
                                   const float* __restrict__ w1,
                                   const float* __restrict__ b1,
                                   float* __restrict__ h1) {
    __shared__ float xs[34][35];
    __shared__ float ws[16 * 9];
    __shared__ float bs[16];

    const int b   = blockIdx.z;
    const int px0 = blockIdx.x * 16, py0 = blockIdx.y * 16;
    const int t   = threadIdx.y * 16 + threadIdx.x;

    if (t < 144) ws[t] = w1[t];
    if (t < 16)  bs[t] = b1[t];

    const float* xb = x + (size_t)b * 65536;
    for (int i = t; i < 34 * 34; i += 256) {
        int r = i / 34, c = i % 34;
        int gy = 2 * py0 - 1 + r, gx = 2 * px0 - 1 + c;
        float v = 0.0f;
        if (gy >= 0 && gy < 256 && gx >= 0 && gx < 256) v = xb[gy * 256 + gx];
        xs[r][c] = v;
    }
    __syncthreads();

    const int ty = threadIdx.y, tx = threadIdx.x;
    for (int oc = 0; oc < 16; oc++) {
        float wv[9];
        #pragma unroll
        for (int j = 0; j < 9; j++) wv[j] = ws[oc * 9 + j];
        const float bias = bs[oc];
        float m = -3.4e38f;
        #pragma unroll
        for (int dy = 0; dy < 2; dy++)
        #pragma unroll
        for (int dx = 0; dx < 2; dx++) {
            float a = 0.0f;
            #pragma unroll
            for (int ky = 0; ky < 3; ky++)
            #pragma unroll
            for (int kx = 0; kx < 3; kx++)
                a = fmaf(xs[2 * ty + dy + ky][2 * tx + dx + kx], wv[ky * 3 + kx], a);
            m = fmaxf(m, __fadd_rn(a, bias));
        }
        h1[(((size_t)b * 16 + oc) * 128 + (py0 + ty)) * 128 + (px0 + tx)] = gelu_exact(m);
    }
}

// ---------------------------------------------------------------------------
// K2: conv2 (16->32), EXACT per-oc chain over (ky,kx,ic) ic-innermost.
// f32x2 over oc pairs; weights via 2x LDS.128 (layout unchanged, static smem).
// ---------------------------------------------------------------------------
__global__ void k2_conv2_pool(const float* __restrict__ h1,
                              const float* __restrict__ w2,
                              const float* __restrict__ b2,
                              float* __restrict__ h2) {
    __shared__ float hs[16][18][18];                       // 20736 B
    __shared__ __align__(16) float wsT[144 * 32];          // 18432 B, [j][oc]
    __shared__ float bs[32];

    const int b   = blockIdx.z;
    const int px0 = blockIdx.x * 8, py0 = blockIdx.y * 8;
    const int t   = threadIdx.x;

    // transpose weights: wsT[j*32+o] = w2[o*144 + j], j = ic*9+ky*3+kx
    for (int i = t; i < 4608; i += 256) {
        int o = i & 31, j = i >> 5;
        wsT[j * 32 + o] = w2[o * 144 + j];
    }
    if (t < 32) bs[t] = b2[t];

    const float* hb = h1 + (size_t)b * 16 * 16384;
    for (int i = t; i < 16 * 18 * 18; i += 256) {
        int ic = i / 324, rem = i % 324;
        int r = rem / 18, c = rem % 18;
        int gy = 2 * py0 - 1 + r, gx = 2 * px0 - 1 + c;
        float v = 0.0f;
        if (gy >= 0 && gy < 128 && gx >= 0 && gx < 128) v = hb[ic * 16384 + gy * 128 + gx];
        hs[ic][r][c] = v;
    }
    __syncthreads();

    const int s  = t & 63, g = t >> 6;   // g: oc-group (8 oc = 4 pairs)
    const int px = s & 7, py = s >> 3;

    ull acc[4][4];
    #pragma unroll
    for (int p = 0; p < 4; p++)
        #pragma unroll
        for (int wv = 0; wv < 4; wv++) acc[p][wv] = 0;

    #pragma unroll
    for (int ky = 0; ky < 3; ky++)
    #pragma unroll
    for (int kx = 0; kx < 3; kx++) {
        for (int ic = 0; ic < 16; ic++) {          // ic innermost (exact order)
            const float u00 = hs[ic][2 * py + 0 + ky][2 * px + 0 + kx];
            const float u01 = hs[ic][2 * py + 0 + ky][2 * px + 1 + kx];
            const float u10 = hs[ic][2 * py + 1 + ky][2 * px + 0 + kx];
            const float u11 = hs[ic][2 * py + 1 + ky][2 * px + 1 + kx];
            const ull s00 = pk2(u00, u00), s01 = pk2(u01, u01);
            const ull s10 = pk2(u10, u10), s11 = pk2(u11, u11);
            const int j = ic * 9 + ky * 3 + kx;
            const ulonglong2* wrow = (const ulonglong2*)(wsT + j * 32 + g * 8);
            const ulonglong2 wA = wrow[0], wB = wrow[1];
            acc[0][0] = fma2(wA.x, s00, acc[0][0]);
            acc[0][1] = fma2(wA.x, s01, acc[0][1]);
            acc[0][2] = fma2(wA.x, s10, acc[0][2]);
            acc[0][3] = fma2(wA.x, s11, acc[0][3]);
            acc[1][0] = fma2(wA.y, s00, acc[1][0]);
            acc[1][1] = fma2(wA.y, s01, acc[1][1]);
            acc[1][2] = fma2(wA.y, s10, acc[1][2]);
            acc[1][3] = fma2(wA.y, s11, acc[1][3]);
            acc[2][0] = fma2(wB.x, s00, acc[2][0]);
            acc[2][1] = fma2(wB.x, s01, acc[2][1]);
            acc[2][2] = fma2(wB.x, s10, acc[2][2]);
            acc[2][3] = fma2(wB.x, s11, acc[2][3]);
            acc[3][0] = fma2(wB.y, s00, acc[3][0]);
            acc[3][1] = fma2(wB.y, s01, acc[3][1]);
            acc[3][2] = fma2(wB.y, s10, acc[3][2]);
            acc[3][3] = fma2(wB.y, s11, acc[3][3]);
        }
    }

    #pragma unroll
    for (int p = 0; p < 4; p++) {
        float a0[4], a1[4];
        #pragma unroll
        for (int wv = 0; wv < 4; wv++) upk2(acc[p][wv], a0[wv], a1[wv]);
        const int oc0 = g * 8 + 2 * p, oc1 = oc0 + 1;
        const float bb0 = bs[oc0], bb1 = bs[oc1];
        float m0 = fmaxf(fmaxf(__fadd_rn(a0[0], bb0), __fadd_rn(a0[1], bb0)),
                         fmaxf(__fadd_rn(a0[2], bb0), __fadd_rn(a0[3], bb0)));
        float m1 = fmaxf(fmaxf(__fadd_rn(a1[0], bb1), __fadd_rn(a1[1], bb1)),
                         fmaxf(__fadd_rn(a1[2], bb1), __fadd_rn(a1[3], bb1)));
        h2[(((size_t)b * 32 + oc0) * 64 + (py0 + py)) * 64 + (px0 + px)] = m0;
        h2[(((size_t)b * 32 + oc1) * 64 + (py0 + py)) * 64 + (px0 + px)] = m1;
    }
}

// ---------------------------------------------------------------------------
// K3: VQ (EXACT per vector). 2 vectors per thread (as in R9 873us baseline).
// grid 512, block 256, dyn smem 67584 B.
// ---------------------------------------------------------------------------
__global__ void __launch_bounds__(256, 2)
k3_vq(const float* __restrict__ h2,
      const float* __restrict__ cb,
      float* __restrict__ q,
      float* __restrict__ outF,
      float* __restrict__ partial) {
    extern __shared__ __align__(16) float sm[];
    float* scbT = sm;             // [32][512]
    float* sc2  = sm + 32 * 512;  // [512]
    const int t = threadIdx.x;

    for (int i = t; i < 32 * 512; i += 256) {
        int d = i >> 9, k = i & 511;
        scbT[i] = cb[k * 32 + d];
    }
    for (int k = t; k < 512; k += 256) {
        const float* c = cb + k * 32;
        float s = 0.0f;
        #pragma unroll
        for (int d = 0; d < 32; d++) s = __fadd_rn(s, __fmul_rn(c[d], c[d]));
        sc2[k] = s;
    }
    __syncthreads();

    const int vA = blockIdx.x * 256 + t;        // [0, 131072)
    const int vB = vA + 131072;
    const int bA = vA >> 12, pA = vA & 4095;
    const int bB = vB >> 12, pB = vB & 4095;
    const float* hA = h2 + ((size_t)bA * 32) * 4096 + pA;
    const float* hB = h2 + ((size_t)bB * 32) * 4096 + pB;

    float xvA[32], xvB[32];
    float x2A = 0.0f, x2B = 0.0f;
    #pragma unroll
    for (int d = 0; d < 32; d++) {
        xvA[d] = hA[(size_t)d * 4096];
        xvB[d] = hB[(size_t)d * 4096];
        x2A = __fadd_rn(x2A, __fmul_rn(xvA[d], xvA[d]));
        x2B = __fadd_rn(x2B, __fmul_rn(xvB[d], xvB[d]));
    }

    float bestA = 3.4e38f, bestB = 3.4e38f;
    int biA = 0, biB = 0;
    for (int k0 = 0; k0 < 512; k0 += 8) {
        ull aA0 = 0, aA1 = 0, aA2 = 0, aA3 = 0;
        ull aB0 = 0, aB1 = 0, aB2 = 0, aB3 = 0;
        #pragma unroll
        for (int d = 0; d < 32; d++) {
            const ulonglong2* row = (const ulonglong2*)(scbT + d * 512 + k0);
            const ulonglong2 rA = row[0], rB = row[1];
            const ull xa = pk2(xvA[d], xvA[d]);
            const ull xb = pk2(xvB[d], xvB[d]);
            aA0 = fma2(rA.x, xa, aA0); aA1 = fma2(rA.y, xa, aA1);
            aA2 = fma2(rB.x, xa, aA2); aA3 = fma2(rB.y, xa, aA3);
            aB0 = fma2(rA.x, xb, aB0); aB1 = fma2(rA.y, xb, aB1);
            aB2 = fma2(rB.x, xb, aB2); aB3 = fma2(rB.y, xb, aB3);
        }
        float xcA[8], xcB[8];
        upk2(aA0, xcA[0], xcA[1]); upk2(aA1, xcA[2], xcA[3]);
        upk2(aA2, xcA[4], xcA[5]); upk2(aA3, xcA[6], xcA[7]);
        upk2(aB0, xcB[0], xcB[1]); upk2(aB1, xcB[2], xcB[3]);
        upk2(aB2, xcB[4], xcB[5]); upk2(aB3, xcB[6], xcB[7]);
        #pragma unroll
        for (int j = 0; j < 8; j++) {
            const float c2 = sc2[k0 + j];
            const float dA = __fadd_rn(__fsub_rn(x2A, __fmul_rn(2.0f, xcA[j])), c2);
            const float dB = __fadd_rn(__fsub_rn(x2B, __fmul_rn(2.0f, xcB[j])), c2);
            if (dA < bestA) { bestA = dA; biA = k0 + j; }
            if (dB < bestB) { bestB = dB; biB = k0 + j; }
        }
    }

    float err = 0.0f;
    {
        const float* c = cb + biA * 32;
        float* qb = q + ((size_t)bA * 32) * 4096 + pA;
        #pragma unroll
        for (int d = 0; d < 32; d++) {
            const float e = __fsub_rn(c[d], xvA[d]);
            err = __fadd_rn(err, __fmul_rn(e, e));
            qb[(size_t)d * 4096] = __fadd_rn(xvA[d], e);
        }
        outF[4194304 + vA] = (float)biA;
    }
    {
        const float* c = cb + biB * 32;
        float* qb = q + ((size_t)bB * 32) * 4096 + pB;
        #pragma unroll
        for (int d = 0; d < 32; d++) {
            const float e = __fsub_rn(c[d], xvB[d]);
            err = __fadd_rn(err, __fmul_rn(e, e));
            qb[(size_t)d * 4096] = __fadd_rn(xvB[d], e);
        }
        outF[4194304 + vB] = (float)biB;
    }

    __shared__ float red[256];
    red[t] = err;
    __syncthreads();
    #pragma unroll
    for (int s2 = 128; s2 > 0; s2 >>= 1) {
        if (t < s2) red[t] += red[t + s2];
        __syncthreads();
    }
    if (t == 0) partial[blockIdx.x] = red[0];
}

// ---------------------------------------------------------------------------
// K4: upsample2 + conv3 + bias + gelu, PHASE-DECOMPOSED (image path).
// Non-duplicated q tile (R9), cw layout [ph][c][tap][oc16] -> 4x LDS.128 per
// tap. Tile 32x16 out, 2 px/thread. grid (4,8,B), dyn smem 55872 B.
// ---------------------------------------------------------------------------
__global__ void k4_up_conv3_gelu(const float* __restrict__ q,
                                 const float* __restrict__ w3,
                                 const float* __restrict__ b3,
                                 float* __restrict__ h3) {
    extern __shared__ __align__(16) float sm4[];
    float* qs = sm4;                 // 5760 floats (q tile [32][10][18]); temp for raw w3
    float* cw = sm4 + 5760;          // 8192 floats: [ph][c][tap][oc16]
    float* bs = sm4 + 13952;         // 16

    const int b   = blockIdx.z;
    const int ox0 = blockIdx.x * 32, oy0 = blockIdx.y * 16;
    const int t   = threadIdx.x;

    // stage raw w3 into qs-as-temp
    for (int i = t; i < 4608; i += 256) qs[i] = w3[i];
    if (t < 16) bs[t] = b3[t];
    __syncthreads();

    // combined weights: cw[((ph*32+c)*4+tap)*16+o]
    for (int e = t; e < 8192; e += 256) {
        const int o = e & 15, tap = (e >> 4) & 3, c = (e >> 6) & 31, ph = e >> 11;
        const int tx = tap & 1, ty = tap >> 1, dx = ph & 1, dy = ph >> 1;
        const int ys = dy ? (ty ? 2 : 0) : (ty ? 1 : 0);
        const int yc = dy ? (ty ? 1 : 2) : (ty ? 2 : 1);
        const int xs = dx ? (tx ? 2 : 0) : (tx ? 1 : 0);
        const int xc = dx ? (tx ? 1 : 2) : (tx ? 2 : 1);
        float ssum = 0.0f;
        for (int iy = 0; iy < yc; iy++)
            for (int ix = 0; ix < xc; ix++)
                ssum += qs[o * 288 + c * 9 + (ys + iy) * 3 + (xs + ix)];
        cw[e] = ssum;
    }
    __syncthreads();

    // q tile [32][10][18], zero-filled OOB
    const int qyb = (oy0 >> 1) - 1, qxb = (ox0 >> 1) - 1;
    const float* qb_ = q + (size_t)b * 131072;
    for (int i = t; i < 5760; i += 256) {
        const int c = i / 180, rem = i % 180, r = rem / 18, cc = rem % 18;
        const int gy = qyb + r, gx = qxb + cc;
        float v = 0.0f;
        if (gy >= 0 && gy < 64 && gx >= 0 && gx < 64) v = qb_[c * 4096 + gy * 64 + gx];
        qs[c * 180 + r * 18 + cc] = v;
    }
    __syncthreads();

    const int wrp = t >> 5, lane = t & 31;
    const int dx = wrp & 1, dy = (wrp >> 1) & 1, sub = wrp >> 2;
    const int ph = dy * 2 + dx;
    const int idxA = sub * 32 + lane, idxB = idxA + 64;
    const int uxA = idxA & 15, uyA = idxA >> 4;
    const int uxB = idxB & 15, uyB = idxB >> 4;
    const int jxA = uxA + dx, jyA = uyA + dy;
    const int jxB = uxB + dx, jyB = uyB + dy;

    ull A[8], B[8];
    #pragma unroll
    for (int p = 0; p < 8; p++) { A[p] = 0; B[p] = 0; }

    const float* cwp = cw + ph * 2048;
    for (int c = 0; c < 32; c++) {
        const float* qc = qs + c * 180;
        const float a00 = qc[jyA * 18 + jxA],       a01 = qc[jyA * 18 + jxA + 1];
        const float a10 = qc[(jyA + 1) * 18 + jxA], a11 = qc[(jyA + 1) * 18 + jxA + 1];
        const float b00 = qc[jyB * 18 + jxB],       b01 = qc[jyB * 18 + jxB + 1];
        const float b10 = qc[(jyB + 1) * 18 + jxB], b11 = qc[(jyB + 1) * 18 + jxB + 1];
        const ull sa[4] = { pk2(a00, a00), pk2(a01, a01), pk2(a10, a10), pk2(a11, a11) };
        const ull sb[4] = { pk2(b00, b00), pk2(b01, b01), pk2(b10, b10), pk2(b11, b11) };
        #pragma unroll
        for (int tap = 0; tap < 4; tap++) {
            const ulonglong2* wr = (const ulonglong2*)(cwp + (c * 4 + tap) * 16);
            #pragma unroll
            for (int h = 0; h < 4; h++) {
                const ulonglong2 wv = wr[h];
                A[2*h  ] = fma2(wv.x, sa[tap], A[2*h  ]);
                A[2*h+1] = fma2(wv.y, sa[tap], A[2*h+1]);
                B[2*h  ] = fma2(wv.x, sb[tap], B[2*h  ]);
                B[2*h+1] = fma2(wv.y, sb[tap], B[2*h+1]);
            }
        }
    }

    const int oxA = ox0 + 2 * uxA + dx, oyA = oy0 + 2 * uyA + dy;
    const int oxB = ox0 + 2 * uxB + dx, oyB = oy0 + 2 * uyB + dy;
    #pragma unroll
    for (int p = 0; p < 8; p++) {
        float a0, a1, c0, c1;
        upk2(A[p], a0, a1);
        upk2(B[p], c0, c1);
        h3[(((size_t)b * 16 + 2 * p + 0) * 128 + oyA) * 128 + oxA] = gelu_fast(a0 + bs[2 * p + 0]);
        h3[(((size_t)b * 16 + 2 * p + 1) * 128 + oyA) * 128 + oxA] = gelu_fast(a1 + bs[2 * p + 1]);
        h3[(((size_t)b * 16 + 2 * p + 0) * 128 + oyB) * 128 + oxB] = gelu_fast(c0 + bs[2 * p + 0]);
        h3[(((size_t)b * 16 + 2 * p + 1) * 128 + oyB) * 128 + oxB] = gelu_fast(c1 + bs[2 * p + 1]);
    }
}

// ---------------------------------------------------------------------------
// K5: upsample2 + conv4 (16->1) + clip, PHASE-DECOMPOSED (image path).
// Tile 32x32 out, 4 px/thread. grid (8,8,B).
// ---------------------------------------------------------------------------
__global__ void k5_up_conv4_clip(const float* __restrict__ h3,
                                 const float* __restrict__ w4,
                                 const float* __restrict__ b4,
                                 float* __restrict__ outF) {
    __shared__ float hs[16 * 18 * 18];
    __shared__ float cw5[256];
    __shared__ float wtmp[144];

    const int b   = blockIdx.z;
    const int ox0 = blockIdx.x * 32, oy0 = blockIdx.y * 32;
    const int t   = threadIdx.x;

    if (t < 144) wtmp[t] = w4[t];
    __syncthreads();

    {
        const int c = t & 15, tap = (t >> 4) & 3, ph = t >> 6;
        const int tx = tap & 1, ty = tap >> 1, dx = ph & 1, dy = ph >> 1;
        const int ys = dy ? (ty ? 2 : 0) : (ty ? 1 : 0);
        const int yc = dy ? (ty ? 1 : 2) : (ty ? 2 : 1);
        const int xs = dx ? (tx ? 2 : 0) : (tx ? 1 : 0);
        const int xc = dx ? (tx ? 1 : 2) : (tx ? 2 : 1);
        float ssum = 0.0f;
        for (int iy = 0; iy < yc; iy++)
            for (int ix = 0; ix < xc; ix++)
                ssum += wtmp[c * 9 + (ys + iy) * 3 + (xs + ix)];
        cw5[t] = ssum;
    }

    const int qyb = (oy0 >> 1) - 1, qxb = (ox0 >> 1) - 1;
    const float* hb = h3 + (size_t)b * 16 * 16384;
    for (int i = t; i < 16 * 324; i += 256) {
        const int c = i / 324, rem = i % 324, r = rem / 18, cc = rem % 18;
        const int gy = qyb + r, gx = qxb + cc;
        float v = 0.0f;
        if (gy >= 0 && gy < 128 && gx >= 0 && gx < 128) v = hb[c * 16384 + gy * 128 + gx];
        hs[c * 324 + r * 18 + cc] = v;
    }
    __syncthreads();

    const int wrp = t >> 5, lane = t & 31;
    const int dx = wrp & 1, dy = (wrp >> 1) & 1, sub = wrp >> 2;
    const float* cwp = cw5 + (dy * 2 + dx) * 64;
    const float bias = b4[0];

    int jx[4], jy[4], ox[4], oy[4];
    #pragma unroll
    for (int i = 0; i < 4; i++) {
        const int idx = sub * 32 + lane + 64 * i;
        const int ux = idx & 15, uy = idx >> 4;
        jx[i] = ux + dx; jy[i] = uy + dy;
        ox[i] = ox0 + 2 * ux + dx; oy[i] = oy0 + 2 * uy + dy;
    }

    float acc[4] = {0.f, 0.f, 0.f, 0.f};
    for (int c = 0; c < 16; c++) {
        const float w00 = cwp[c], w01 = cwp[16 + c], w10 = cwp[32 + c], w11 = cwp[48 + c];
        const float* hc = hs + c * 324;
        #pragma unroll
        for (int i = 0; i < 4; i++) {
            acc[i] = fmaf(hc[jy[i] * 18 + jx[i]],           w00, acc[i]);
            acc[i] = fmaf(hc[jy[i] * 18 + jx[i] + 1],       w01, acc[i]);
            acc[i] = fmaf(hc[(jy[i] + 1) * 18 + jx[i]],     w10, acc[i]);
            acc[i] = fmaf(hc[(jy[i] + 1) * 18 + jx[i] + 1], w11, acc[i]);
        }
    }

    #pragma unroll
    for (int i = 0; i < 4; i++) {
        float a = acc[i] + bias;
        a = fminf(fmaxf(a, -1.0f), 1.0f);
        outF[(size_t)b * 65536 + oy[i] * 256 + ox[i]] = a;
    }
}

// ---------------------------------------------------------------------------
// K6: deterministic final reduction of commit loss (512 partials).
// ---------------------------------------------------------------------------
__global__ void k6_loss(const float* __restrict__ partial, float* __restrict__ outF) {
    __shared__ float red[256];
    const int t = threadIdx.x;
    red[t] = partial[t] + partial[t + 256];
    __syncthreads();
    #pragma unroll
    for (int s2 = 128; s2 > 0; s2 >>= 1) {
        if (t < s2) red[t] += red[t + s2];
        __syncthreads();
    }
    if (t == 0) outF[4194304 + 262144] = red[0] * (1.0f / 8388608.0f);
}

// ---------------------------------------------------------------------------
extern "C" void kernel_launch(void* const* d_in, const int* in_sizes, int n_in,
                              void* d_out, int out_size) {
    const float* x  = (const float*)d_in[0];
    const float* w1 = (const float*)d_in[1];
    const float* b1 = (const float*)d_in[2];
    const float* w2 = (const float*)d_in[3];
    const float* b2 = (const float*)d_in[4];
    const float* cb = (const float*)d_in[5];
    const float* w3 = (const float*)d_in[6];
    const float* b3 = (const float*)d_in[7];
    const float* w4 = (const float*)d_in[8];
    const float* b4 = (const float*)d_in[9];
    float* outF = (float*)d_out;

    float *h1, *h2, *q, *h3, *partial;
    cudaGetSymbolAddress((void**)&h1, g_h1);
    cudaGetSymbolAddress((void**)&h2, g_h2);
    cudaGetSymbolAddress((void**)&q,  g_q);
    cudaGetSymbolAddress((void**)&h3, g_h3);
    cudaGetSymbolAddress((void**)&partial, g_partial);

    cudaFuncSetAttribute(k3_vq,            cudaFuncAttributeMaxDynamicSharedMemorySize, 67584);
    cudaFuncSetAttribute(k4_up_conv3_gelu, cudaFuncAttributeMaxDynamicSharedMemorySize, 55872);

    k1_conv1_pool_gelu<<<dim3(8, 8, BATCH), dim3(16, 16)>>>(x, w1, b1, h1);
    k2_conv2_pool<<<dim3(8, 8, BATCH), 256>>>(h1, w2, b2, h2);
    k3_vq<<<512, 256, 67584>>>(h2, cb, q, outF, partial);
    k4_up_conv3_gelu<<<dim3(4, 8, BATCH), 256, 55872>>>(q, w3, b3, h3);
    k5_up_conv4_clip<<<dim3(8, 8, BATCH), 256>>>(h3, w4, b4, outF);
    k6_loss<<<1, 256>>>(partial, outF);
}

// round 13
// speedup vs baseline: 1.2032x; 1.1209x over previous
#include <cuda_runtime.h>
#include <math.h>

// ---------------------------------------------------------------------------
// SimpleVQAutoEncoder forward. k1/k2/k3 bit-exact (XLA-CPU-aligned, decide VQ
// indices); k4/k5 image-only -> re-associated (phase-decomposed).
// R13 = R9 (873us best) + f32x2 k1 (bit-exact) + fast-div gelu in k4.
// Empirical rules honored: LDS.64 broadcasts only; keep >=3-4 CTAs/SM.
// Outputs in d_out (fp32): image | indices | commit_loss
// ---------------------------------------------------------------------------

#define BATCH 64
typedef unsigned long long ull;

__device__ float g_h1[BATCH * 16 * 128 * 128];
__device__ float g_h2[BATCH * 32 * 64 * 64];
__device__ float g_q [BATCH * 32 * 64 * 64];
__device__ float g_h3[BATCH * 16 * 128 * 128];
__device__ float g_partial[1024];

// XLA f32 erf: single rational approximation, clamp to [-4,4]. (exact path)
__device__ __forceinline__ float erf_xla(float x) {
    const float w  = fminf(fmaxf(x, -4.0f), 4.0f);
    const float x2 = __fmul_rn(w, w);
    float p = -2.72614225801306e-10f;
    p = __fadd_rn(__fmul_rn(p, x2),  2.77068142495902e-08f);
    p = __fadd_rn(__fmul_rn(p, x2), -2.10102402082508e-06f);
    p = __fadd_rn(__fmul_rn(p, x2), -5.69250639462346e-05f);
    p = __fadd_rn(__fmul_rn(p, x2), -7.34990630326855e-04f);
    p = __fadd_rn(__fmul_rn(p, x2), -2.95459980854025e-03f);
    p = __fadd_rn(__fmul_rn(p, x2), -1.60960333262415e-02f);
    p = __fmul_rn(w, p);
    float q = -1.45660718464996e-05f;
    q = __fadd_rn(__fmul_rn(q, x2), -2.13374055278905e-04f);
    q = __fadd_rn(__fmul_rn(q, x2), -1.68282697438203e-03f);
    q = __fadd_rn(__fmul_rn(q, x2), -7.37332916720468e-03f);
    q = __fadd_rn(__fmul_rn(q, x2), -1.42647390514189e-02f);
    return __fdiv_rn(p, q);
}

__device__ __forceinline__ float gelu_exact(float v) {
    const float t = __fdiv_rn(v, 1.41421356237309504880f);
    const float e = erf_xla(t);
    return 0.5f * __fmul_rn(v, __fadd_rn(e, 1.0f));
}

// Image-only fast path (k4): same poly, fast division (MUFU.RCP).
__device__ __forceinline__ float erf_fast(float x) {
    const float w  = fminf(fmaxf(x, -4.0f), 4.0f);
    const float x2 = w * w;
    float p = -2.72614225801306e-10f;
    p = fmaf(p, x2,  2.77068142495902e-08f);
    p = fmaf(p, x2, -2.10102402082508e-06f);
    p = fmaf(p, x2, -5.69250639462346e-05f);
    p = fmaf(p, x2, -7.34990630326855e-04f);
    p = fmaf(p, x2, -2.95459980854025e-03f);
    p = fmaf(p, x2, -1.60960333262415e-02f);
    p = w * p;
    float q = -1.45660718464996e-05f;
    q = fmaf(q, x2, -2.13374055278905e-04f);
    q = fmaf(q, x2, -1.68282697438203e-03f);
    q = fmaf(q, x2, -7.37332916720468e-03f);
    q = fmaf(q, x2, -1.42647390514189e-02f);
    return __fdividef(p, q);
}

__device__ __forceinline__ float gelu_fast(float v) {
    const float t = v * 0.70710678118654752440f;
    return 0.5f * v * (1.0f + erf_fast(t));
}

__device__ __forceinline__ ull pk2(float lo, float hi) {
    ull r; asm("mov.b64 %0, {%1, %2};" : "=l"(r) : "f"(lo), "f"(hi)); return r;
}
__device__ __forceinline__ void upk2(ull v, float& lo, float& hi) {
    asm("mov.b64 {%0, %1}, %2;" : "=f"(lo), "=f"(hi) : "l"(v));
}
__device__ __forceinline__ ull fma2(ull a, ull b, ull c) {
    ull r; asm("fma.rn.f32x2 %0, %1, %2, %3;" : "=l"(r) : "l"(a), "l"(b), "l"(c));
    return r;
}

// ---------------------------------------------------------------------------
// K1: conv1 (1->16) + bias-after + maxpool2 + gelu (EXACT chains).
// f32x2 over oc pairs, two halves of 4 pairs to cap registers.
// 16 unique window inputs splatted ONCE. Weights via LDS.64 broadcast.
// Per-lane chain: j=(ky,kx) sequential fma from 0 == R9 scalar order.
// ---------------------------------------------------------------------------
__global__ void k1_conv1_pool_gelu(const float* __restrict__ x,
                                   const float* __restrict__ w1,
                                   const float* __restrict__ b1,
                                   float* __restrict__ h1) {
    __shared__ float xs[34][35];
    __shared__ __align__(8) float wsT[9 * 16];   // [j][oc]
    __shared__ float bs[16];

    const int b   = blockIdx.z;
    const int px0 = blockIdx.x * 16, py0 = blockIdx.y * 16;
    const int ty = threadIdx.y, tx = threadIdx.x;
    const int t  = ty * 16 + tx;

    if (t < 144) { const int j = t >> 4, o = t & 15; wsT[j * 16 + o] = w1[o * 9 + j]; }
    if (t < 16)  bs[t] = b1[t];

    const float* xb = x + (size_t)b * 65536;
    for (int i = t; i < 34 * 34; i += 256) {
        int r = i / 34, c = i % 34;
        int gy = 2 * py0 - 1 + r, gx = 2 * px0 - 1 + c;
        float v = 0.0f;
        if (gy >= 0 && gy < 256 && gx >= 0 && gx < 256) v = xb[gy * 256 + gx];
        xs[r][c] = v;
    }
    __syncthreads();

    // 16 unique conv inputs for this pooled output, splatted once.
    ull xin[16];
    #pragma unroll
    for (int r = 0; r < 4; r++)
        #pragma unroll
        for (int c = 0; c < 4; c++) {
            const float v = xs[2 * ty + r][2 * tx + c];
            xin[r * 4 + c] = pk2(v, v);
        }

    #pragma unroll
    for (int h = 0; h < 2; h++) {        // halves: oc pairs [h*4, h*4+4)
        ull acc[4][4];                   // [pos(dy*2+dx)][pair]
        #pragma unroll
        for (int pos = 0; pos < 4; pos++)
            #pragma unroll
            for (int p = 0; p < 4; p++) acc[pos][p] = 0;

        #pragma unroll
        for (int j = 0; j < 9; j++) {
            const int ky = j / 3, kx = j % 3;
            const ull* wr = (const ull*)(wsT + j * 16) + h * 4;
            #pragma unroll
            for (int p = 0; p < 4; p++) {
                const ull wv = wr[p];
                acc[0][p] = fma2(wv, xin[(0 + ky) * 4 + (0 + kx)], acc[0][p]);
                acc[1][p] = fma2(wv, xin[(0 + ky) * 4 + (1 + kx)], acc[1][p]);
                acc[2][p] = fma2(wv, xin[(1 + ky) * 4 + (0 + kx)], acc[2][p]);
                acc[3][p] = fma2(wv, xin[(1 + ky) * 4 + (1 + kx)], acc[3][p]);
            }
        }

        #pragma unroll
        for (int p = 0; p < 4; p++) {
            float a0[4], a1[4];
            #pragma unroll
            for (int pos = 0; pos < 4; pos++) upk2(acc[pos][p], a0[pos], a1[pos]);
            const int oc0 = h * 8 + 2 * p, oc1 = oc0 + 1;
            const float bb0 = bs[oc0], bb1 = bs[oc1];
            const float m0 = fmaxf(fmaxf(__fadd_rn(a0[0], bb0), __fadd_rn(a0[1], bb0)),
                                   fmaxf(__fadd_rn(a0[2], bb0), __fadd_rn(a0[3], bb0)));
            const float m1 = fmaxf(fmaxf(__fadd_rn(a1[0], bb1), __fadd_rn(a1[1], bb1)),
                                   fmaxf(__fadd_rn(a1[2], bb1), __fadd_rn(a1[3], bb1)));
            h1[(((size_t)b * 16 + oc0) * 128 + (py0 + ty)) * 128 + (px0 + tx)] = gelu_exact(m0);
            h1[(((size_t)b * 16 + oc1) * 128 + (py0 + ty)) * 128 + (px0 + tx)] = gelu_exact(m1);
        }
    }
}

// ---------------------------------------------------------------------------
// K2: conv2 (16->32), EXACT per-oc chain over (ky,kx,ic) ic-innermost.
// f32x2 over oc pairs; weights via LDS.64 broadcast (R9-proven form).
// ---------------------------------------------------------------------------
__global__ void k2_conv2_pool(const float* __restrict__ h1,
                              const float* __restrict__ w2,
                              const float* __restrict__ b2,
                              float* __restrict__ h2) {
    __shared__ float hs[16][18][18];                 // 20736 B
    __shared__ __align__(8) float wsT[144 * 32];     // 18432 B, [j][oc]
    __shared__ float bs[32];

    const int b   = blockIdx.z;
    const int px0 = blockIdx.x * 8, py0 = blockIdx.y * 8;
    const int t   = threadIdx.x;

    for (int i = t; i < 4608; i += 256) {
        int o = i & 31, j = i >> 5;
        wsT[j * 32 + o] = w2[o * 144 + j];
    }
    if (t < 32) bs[t] = b2[t];

    const float* hb = h1 + (size_t)b * 16 * 16384;
    for (int i = t; i < 16 * 18 * 18; i += 256) {
        int ic = i / 324, rem = i % 324;
        int r = rem / 18, c = rem % 18;
        int gy = 2 * py0 - 1 + r, gx = 2 * px0 - 1 + c;
        float v = 0.0f;
        if (gy >= 0 && gy < 128 && gx >= 0 && gx < 128) v = hb[ic * 16384 + gy * 128 + gx];
        hs[ic][r][c] = v;
    }
    __syncthreads();

    const int s  = t & 63, g = t >> 6;   // g: oc-group (8 oc = 4 pairs)
    const int px = s & 7, py = s >> 3;

    ull acc[4][4];
    #pragma unroll
    for (int p = 0; p < 4; p++)
        #pragma unroll
        for (int wv = 0; wv < 4; wv++) acc[p][wv] = 0;

    #pragma unroll
    for (int ky = 0; ky < 3; ky++)
    #pragma unroll
    for (int kx = 0; kx < 3; kx++) {
        for (int ic = 0; ic < 16; ic++) {          // ic innermost (exact order)
            const float u00 = hs[ic][2 * py + 0 + ky][2 * px + 0 + kx];
            const float u01 = hs[ic][2 * py + 0 + ky][2 * px + 1 + kx];
            const float u10 = hs[ic][2 * py + 1 + ky][2 * px + 0 + kx];
            const float u11 = hs[ic][2 * py + 1 + ky][2 * px + 1 + kx];
            const ull s00 = pk2(u00, u00), s01 = pk2(u01, u01);
            const ull s10 = pk2(u10, u10), s11 = pk2(u11, u11);
            const int j = ic * 9 + ky * 3 + kx;
            const ull* wrow = (const ull*)(wsT + j * 32) + g * 4;
            #pragma unroll
            for (int p = 0; p < 4; p++) {
                const ull wp = wrow[p];
                acc[p][0] = fma2(wp, s00, acc[p][0]);
                acc[p][1] = fma2(wp, s01, acc[p][1]);
                acc[p][2] = fma2(wp, s10, acc[p][2]);
                acc[p][3] = fma2(wp, s11, acc[p][3]);
            }
        }
    }

    #pragma unroll
    for (int p = 0; p < 4; p++) {
        float a0[4], a1[4];
        #pragma unroll
        for (int wv = 0; wv < 4; wv++) upk2(acc[p][wv], a0[wv], a1[wv]);
        const int oc0 = g * 8 + 2 * p, oc1 = oc0 + 1;
        const float bb0 = bs[oc0], bb1 = bs[oc1];
        float m0 = fmaxf(fmaxf(__fadd_rn(a0[0], bb0), __fadd_rn(a0[1], bb0)),
                         fmaxf(__fadd_rn(a0[2], bb0), __fadd_rn(a0[3], bb0)));
        float m1 = fmaxf(fmaxf(__fadd_rn(a1[0], bb1), __fadd_rn(a1[1], bb1)),
                         fmaxf(__fadd_rn(a1[2], bb1), __fadd_rn(a1[3], bb1)));
        h2[(((size_t)b * 32 + oc0) * 64 + (py0 + py)) * 64 + (px0 + px)] = m0;
        h2[(((size_t)b * 32 + oc1) * 64 + (py0 + py)) * 64 + (px0 + px)] = m1;
    }
}

// ---------------------------------------------------------------------------
// K3: VQ (EXACT per vector). 2 vectors per thread (R9-proven form).
// grid 512, block 256, dyn smem 67584 B.
// ---------------------------------------------------------------------------
__global__ void __launch_bounds__(256, 2)
k3_vq(const float* __restrict__ h2,
      const float* __restrict__ cb,
      float* __restrict__ q,
      float* __restrict__ outF,
      float* __restrict__ partial) {
    extern __shared__ __align__(16) float sm[];
    float* scbT = sm;             // [32][512]
    float* sc2  = sm + 32 * 512;  // [512]
    const int t = threadIdx.x;

    for (int i = t; i < 32 * 512; i += 256) {
        int d = i >> 9, k = i & 511;
        scbT[i] = cb[k * 32 + d];
    }
    for (int k = t; k < 512; k += 256) {
        const float* c = cb + k * 32;
        float s = 0.0f;
        #pragma unroll
        for (int d = 0; d < 32; d++) s = __fadd_rn(s, __fmul_rn(c[d], c[d]));
        sc2[k] = s;
    }
    __syncthreads();

    const int vA = blockIdx.x * 256 + t;        // [0, 131072)
    const int vB = vA + 131072;
    const int bA = vA >> 12, pA = vA & 4095;
    const int bB = vB >> 12, pB = vB & 4095;
    const float* hA = h2 + ((size_t)bA * 32) * 4096 + pA;
    const float* hB = h2 + ((size_t)bB * 32) * 4096 + pB;

    float xvA[32], xvB[32];
    float x2A = 0.0f, x2B = 0.0f;
    #pragma unroll
    for (int d = 0; d < 32; d++) {
        xvA[d] = hA[(size_t)d * 4096];
        xvB[d] = hB[(size_t)d * 4096];
        x2A = __fadd_rn(x2A, __fmul_rn(xvA[d], xvA[d]));
        x2B = __fadd_rn(x2B, __fmul_rn(xvB[d], xvB[d]));
    }

    float bestA = 3.4e38f, bestB = 3.4e38f;
    int biA = 0, biB = 0;
    for (int k0 = 0; k0 < 512; k0 += 8) {
        ull aA0 = 0, aA1 = 0, aA2 = 0, aA3 = 0;
        ull aB0 = 0, aB1 = 0, aB2 = 0, aB3 = 0;
        #pragma unroll
        for (int d = 0; d < 32; d++) {
            const ull* row = (const ull*)(scbT + d * 512 + k0);
            const ull r0 = row[0], r1 = row[1], r2 = row[2], r3 = row[3];
            const ull xa = pk2(xvA[d], xvA[d]);
            const ull xb = pk2(xvB[d], xvB[d]);
            aA0 = fma2(r0, xa, aA0); aA1 = fma2(r1, xa, aA1);
            aA2 = fma2(r2, xa, aA2); aA3 = fma2(r3, xa, aA3);
            aB0 = fma2(r0, xb, aB0); aB1 = fma2(r1, xb, aB1);
            aB2 = fma2(r2, xb, aB2); aB3 = fma2(r3, xb, aB3);
        }
        float xcA[8], xcB[8];
        upk2(aA0, xcA[0], xcA[1]); upk2(aA1, xcA[2], xcA[3]);
        upk2(aA2, xcA[4], xcA[5]); upk2(aA3, xcA[6], xcA[7]);
        upk2(aB0, xcB[0], xcB[1]); upk2(aB1, xcB[2], xcB[3]);
        upk2(aB2, xcB[4], xcB[5]); upk2(aB3, xcB[6], xcB[7]);
        #pragma unroll
        for (int j = 0; j < 8; j++) {
            const float c2 = sc2[k0 + j];
            const float dA = __fadd_rn(__fsub_rn(x2A, __fmul_rn(2.0f, xcA[j])), c2);
            const float dB = __fadd_rn(__fsub_rn(x2B, __fmul_rn(2.0f, xcB[j])), c2);
            if (dA < bestA) { bestA = dA; biA = k0 + j; }
            if (dB < bestB) { bestB = dB; biB = k0 + j; }
        }
    }

    float err = 0.0f;
    {
        const float* c = cb + biA * 32;
        float* qb = q + ((size_t)bA * 32) * 4096 + pA;
        #pragma unroll
        for (int d = 0; d < 32; d++) {
            const float e = __fsub_rn(c[d], xvA[d]);
            err = __fadd_rn(err, __fmul_rn(e, e));
            qb[(size_t)d * 4096] = __fadd_rn(xvA[d], e);
        }
        outF[4194304 + vA] = (float)biA;
    }
    {
        const float* c = cb + biB * 32;
        float* qb = q + ((size_t)bB * 32) * 4096 + pB;
        #pragma unroll
        for (int d = 0; d < 32; d++) {
            const float e = __fsub_rn(c[d], xvB[d]);
            err = __fadd_rn(err, __fmul_rn(e, e));
            qb[(size_t)d * 4096] = __fadd_rn(xvB[d], e);
        }
        outF[4194304 + vB] = (float)biB;
    }

    __shared__ float red[256];
    red[t] = err;
    __syncthreads();
    #pragma unroll
    for (int s2 = 128; s2 > 0; s2 >>= 1) {
        if (t < s2) red[t] += red[t + s2];
        __syncthreads();
    }
    if (t == 0) partial[blockIdx.x] = red[0];
}

// ---------------------------------------------------------------------------
// K4: upsample2 + conv3 + bias + gelu, PHASE-DECOMPOSED (image path).
// R9-proven form: cw [ph][tap][c][oc16], LDS.64 weight broadcasts.
// Tile 32x16 out, 2 px/thread. grid (4,8,B), dyn smem 55872 B.
// ---------------------------------------------------------------------------
__global__ void k4_up_conv3_gelu(const float* __restrict__ q,
                                 const float* __restrict__ w3,
                                 const float* __restrict__ b3,
                                 float* __restrict__ h3) {
    extern __shared__ __align__(16) float sm4[];
    float* qs = sm4;                 // 5760 floats (q tile [32][10][18]); temp for raw w3
    float* cw = sm4 + 5760;          // 8192 floats: [ph][tap][c][oc16]
    float* bs = sm4 + 13952;         // 16

    const int b   = blockIdx.z;
    const int ox0 = blockIdx.x * 32, oy0 = blockIdx.y * 16;
    const int t   = threadIdx.x;

    // stage raw w3 into qs-as-temp
    for (int i = t; i < 4608; i += 256) qs[i] = w3[i];
    if (t < 16) bs[t] = b3[t];
    __syncthreads();

    // combined weights: cw[((ph*4+tap)*32+c)*16+o]
    for (int e = t; e < 8192; e += 256) {
        const int o = e & 15, c = (e >> 4) & 31, tap = (e >> 9) & 3, ph = e >> 11;
        const int tx = tap & 1, ty = tap >> 1, dx = ph & 1, dy = ph >> 1;
        const int ys = dy ? (ty ? 2 : 0) : (ty ? 1 : 0);
        const int yc = dy ? (ty ? 1 : 2) : (ty ? 2 : 1);
        const int xs = dx ? (tx ? 2 : 0) : (tx ? 1 : 0);
        const int xc = dx ? (tx ? 1 : 2) : (tx ? 2 : 1);
        float ssum = 0.0f;
        for (int iy = 0; iy < yc; iy++)
            for (int ix = 0; ix < xc; ix++)
                ssum += qs[o * 288 + c * 9 + (ys + iy) * 3 + (xs + ix)];
        cw[e] = ssum;
    }
    __syncthreads();

    // q tile [32][10][18], zero-filled OOB
    const int qyb = (oy0 >> 1) - 1, qxb = (ox0 >> 1) - 1;
    const float* qb_ = q + (size_t)b * 131072;
    for (int i = t; i < 5760; i += 256) {
        const int c = i / 180, rem = i % 180, r = rem / 18, cc = rem % 18;
        const int gy = qyb + r, gx = qxb + cc;
        float v = 0.0f;
        if (gy >= 0 && gy < 64 && gx >= 0 && gx < 64) v = qb_[c * 4096 + gy * 64 + gx];
        qs[c * 180 + r * 18 + cc] = v;
    }
    __syncthreads();

    const int wrp = t >> 5, lane = t & 31;
    const int dx = wrp & 1, dy = (wrp >> 1) & 1, sub = wrp >> 2;
    const int ph = dy * 2 + dx;
    const int idxA = sub * 32 + lane, idxB = idxA + 64;
    const int uxA = idxA & 15, uyA = idxA >> 4;
    const int uxB = idxB & 15, uyB = idxB >> 4;
    const int jxA = uxA + dx, jyA = uyA + dy;
    const int jxB = uxB + dx, jyB = uyB + dy;

    ull A[8], B[8];
    #pragma unroll
    for (int p = 0; p < 8; p++) { A[p] = 0; B[p] = 0; }

    const float* cwp = cw + ph * 2048;
    for (int c = 0; c < 32; c++) {
        const float* qc = qs + c * 180;
        const float a00 = qc[jyA * 18 + jxA],       a01 = qc[jyA * 18 + jxA + 1];
        const float a10 = qc[(jyA + 1) * 18 + jxA], a11 = qc[(jyA + 1) * 18 + jxA + 1];
        const float b00 = qc[jyB * 18 + jxB],       b01 = qc[jyB * 18 + jxB + 1];
        const float b10 = qc[(jyB + 1) * 18 + jxB], b11 = qc[(jyB + 1) * 18 + jxB + 1];
        const ull sa[4] = { pk2(a00, a00), pk2(a01, a01), pk2(a10, a10), pk2(a11, a11) };
        const ull sb[4] = { pk2(b00, b00), pk2(b01, b01), pk2(b10, b10), pk2(b11, b11) };
        #pragma unroll
        for (int tap = 0; tap < 4; tap++) {
            const ull* wr = (const ull*)(cwp + (tap * 32 + c) * 16);
            #pragma unroll
            for (int p = 0; p < 8; p++) {
                const ull wv = wr[p];
                A[p] = fma2(wv, sa[tap], A[p]);
                B[p] = fma2(wv, sb[tap], B[p]);
            }
        }
    }

    const int oxA = ox0 + 2 * uxA + dx, oyA = oy0 + 2 * uyA + dy;
    const int oxB = ox0 + 2 * uxB + dx, oyB = oy0 + 2 * uyB + dy;
    #pragma unroll
    for (int p = 0; p < 8; p++) {
        float a0, a1, c0, c1;
        upk2(A[p], a0, a1);
        upk2(B[p], c0, c1);
        h3[(((size_t)b * 16 + 2 * p + 0) * 128 + oyA) * 128 + oxA] = gelu_fast(a0 + bs[2 * p + 0]);
        h3[(((size_t)b * 16 + 2 * p + 1) * 128 + oyA) * 128 + oxA] = gelu_fast(a1 + bs[2 * p + 1]);
        h3[(((size_t)b * 16 + 2 * p + 0) * 128 + oyB) * 128 + oxB] = gelu_fast(c0 + bs[2 * p + 0]);
        h3[(((size_t)b * 16 + 2 * p + 1) * 128 + oyB) * 128 + oxB] = gelu_fast(c1 + bs[2 * p + 1]);
    }
}

// ---------------------------------------------------------------------------
// K5: upsample2 + conv4 (16->1) + clip, PHASE-DECOMPOSED (image path).
// Tile 32x32 out, 4 px/thread. grid (8,8,B).
// ---------------------------------------------------------------------------
__global__ void k5_up_conv4_clip(const float* __restrict__ h3,
                                 const float* __restrict__ w4,
                                 const float* __restrict__ b4,
                                 float* __restrict__ outF) {
    __shared__ float hs[16 * 18 * 18];
    __shared__ float cw5[256];
    __shared__ float wtmp[144];

    const int b   = blockIdx.z;
    const int ox0 = blockIdx.x * 32, oy0 = blockIdx.y * 32;
    const int t   = threadIdx.x;

    if (t < 144) wtmp[t] = w4[t];
    __syncthreads();

    {
        const int c = t & 15, tap = (t >> 4) & 3, ph = t >> 6;
        const int tx = tap & 1, ty = tap >> 1, dx = ph & 1, dy = ph >> 1;
        const int ys = dy ? (ty ? 2 : 0) : (ty ? 1 : 0);
        const int yc = dy ? (ty ? 1 : 2) : (ty ? 2 : 1);
        const int xs = dx ? (tx ? 2 : 0) : (tx ? 1 : 0);
        const int xc = dx ? (tx ? 1 : 2) : (tx ? 2 : 1);
        float ssum = 0.0f;
        for (int iy = 0; iy < yc; iy++)
            for (int ix = 0; ix < xc; ix++)
                ssum += wtmp[c * 9 + (ys + iy) * 3 + (xs + ix)];
        cw5[t] = ssum;
    }

    const int qyb = (oy0 >> 1) - 1, qxb = (ox0 >> 1) - 1;
    const float* hb = h3 + (size_t)b * 16 * 16384;
    for (int i = t; i < 16 * 324; i += 256) {
        const int c = i / 324, rem = i % 324, r = rem / 18, cc = rem % 18;
        const int gy = qyb + r, gx = qxb + cc;
        float v = 0.0f;
        if (gy >= 0 && gy < 128 && gx >= 0 && gx < 128) v = hb[c * 16384 + gy * 128 + gx];
        hs[c * 324 + r * 18 + cc] = v;
    }
    __syncthreads();

    const int wrp = t >> 5, lane = t & 31;
    const int dx = wrp & 1, dy = (wrp >> 1) & 1, sub = wrp >> 2;
    const float* cwp = cw5 + (dy * 2 + dx) * 64;
    const float bias = b4[0];

    int jx[4], jy[4], ox[4], oy[4];
    #pragma unroll
    for (int i = 0; i < 4; i++) {
        const int idx = sub * 32 + lane + 64 * i;
        const int ux = idx & 15, uy = idx >> 4;
        jx[i] = ux + dx; jy[i] = uy + dy;
        ox[i] = ox0 + 2 * ux + dx; oy[i] = oy0 + 2 * uy + dy;
    }

    float acc[4] = {0.f, 0.f, 0.f, 0.f};
    for (int c = 0; c < 16; c++) {
        const float w00 = cwp[c], w01 = cwp[16 + c], w10 = cwp[32 + c], w11 = cwp[48 + c];
        const float* hc = hs + c * 324;
        #pragma unroll
        for (int i = 0; i < 4; i++) {
            acc[i] = fmaf(hc[jy[i] * 18 + jx[i]],           w00, acc[i]);
            acc[i] = fmaf(hc[jy[i] * 18 + jx[i] + 1],       w01, acc[i]);
            acc[i] = fmaf(hc[(jy[i] + 1) * 18 + jx[i]],     w10, acc[i]);
            acc[i] = fmaf(hc[(jy[i] + 1) * 18 + jx[i] + 1], w11, acc[i]);
        }
    }

    #pragma unroll
    for (int i = 0; i < 4; i++) {
        float a = acc[i] + bias;
        a = fminf(fmaxf(a, -1.0f), 1.0f);
        outF[(size_t)b * 65536 + oy[i] * 256 + ox[i]] = a;
    }
}

// ---------------------------------------------------------------------------
// K6: deterministic final reduction of commit loss (512 partials).
// ---------------------------------------------------------------------------
__global__ void k6_loss(const float* __restrict__ partial, float* __restrict__ outF) {
    __shared__ float red[256];
    const int t = threadIdx.x;
    red[t] = partial[t] + partial[t + 256];
    __syncthreads();
    #pragma unroll
    for (int s2 = 128; s2 > 0; s2 >>= 1) {
        if (t < s2) red[t] += red[t + s2];
        __syncthreads();
    }
    if (t == 0) outF[4194304 + 262144] = red[0] * (1.0f / 8388608.0f);
}

// ---------------------------------------------------------------------------
extern "C" void kernel_launch(void* const* d_in, const int* in_sizes, int n_in,
                              void* d_out, int out_size) {
    const float* x  = (const float*)d_in[0];
    const float* w1 = (const float*)d_in[1];
    const float* b1 = (const float*)d_in[2];
    const float* w2 = (const float*)d_in[3];
    const float* b2 = (const float*)d_in[4];
    const float* cb = (const float*)d_in[5];
    const float* w3 = (const float*)d_in[6];
    const float* b3 = (const float*)d_in[7];
    const float* w4 = (const float*)d_in[8];
    const float* b4 = (const float*)d_in[9];
    float* outF = (float*)d_out;

    float *h1, *h2, *q, *h3, *partial;
    cudaGetSymbolAddress((void**)&h1, g_h1);
    cudaGetSymbolAddress((void**)&h2, g_h2);
    cudaGetSymbolAddress((void**)&q,  g_q);
    cudaGetSymbolAddress((void**)&h3, g_h3);
    cudaGetSymbolAddress((void**)&partial, g_partial);

    cudaFuncSetAttribute(k3_vq,            cudaFuncAttributeMaxDynamicSharedMemorySize, 67584);
    cudaFuncSetAttribute(k4_up_conv3_gelu, cudaFuncAttributeMaxDynamicSharedMemorySize, 55872);

    k1_conv1_pool_gelu<<<dim3(8, 8, BATCH), dim3(16, 16)>>>(x, w1, b1, h1);
    k2_conv2_pool<<<dim3(8, 8, BATCH), 256>>>(h1, w2, b2, h2);
    k3_vq<<<512, 256, 67584>>>(h2, cb, q, outF, partial);
    k4_up_conv3_gelu<<<dim3(4, 8, BATCH), 256, 55872>>>(q, w3, b3, h3);
    k5_up_conv4_clip<<<dim3(8, 8, BATCH), 256>>>(h3, w4, b4, outF);
    k6_loss<<<1, 256>>>(partial, outF);
}

// round 14
// speedup vs baseline: 1.2062x; 1.0025x over previous
#include <cuda_runtime.h>
#include <math.h>

// ---------------------------------------------------------------------------
// SimpleVQAutoEncoder forward. k1/k2/k3 bit-exact (XLA-CPU-aligned, decide VQ
// indices); k4/k5 image-only -> re-associated (phase-decomposed).
// R14 = R13 (866us best) + k3 packed scoring & 16-k blocks (bit-identical
// values) + k4 adjacent-pixel pairing (shares activation column).
// Rules: LDS.64 broadcasts only; preserve occupancy; FMA chains locked.
// Outputs in d_out (fp32): image | indices | commit_loss
// ---------------------------------------------------------------------------

#define BATCH 64
typedef unsigned long long ull;

__device__ float g_h1[BATCH * 16 * 128 * 128];
__device__ float g_h2[BATCH * 32 * 64 * 64];
__device__ float g_q [BATCH * 32 * 64 * 64];
__device__ float g_h3[BATCH * 16 * 128 * 128];
__device__ float g_partial[1024];

// XLA f32 erf: single rational approximation, clamp to [-4,4]. (exact path)
__device__ __forceinline__ float erf_xla(float x) {
    const float w  = fminf(fmaxf(x, -4.0f), 4.0f);
    const float x2 = __fmul_rn(w, w);
    float p = -2.72614225801306e-10f;
    p = __fadd_rn(__fmul_rn(p, x2),  2.77068142495902e-08f);
    p = __fadd_rn(__fmul_rn(p, x2), -2.10102402082508e-06f);
    p = __fadd_rn(__fmul_rn(p, x2), -5.69250639462346e-05f);
    p = __fadd_rn(__fmul_rn(p, x2), -7.34990630326855e-04f);
    p = __fadd_rn(__fmul_rn(p, x2), -2.95459980854025e-03f);
    p = __fadd_rn(__fmul_rn(p, x2), -1.60960333262415e-02f);
    p = __fmul_rn(w, p);
    float q = -1.45660718464996e-05f;
    q = __fadd_rn(__fmul_rn(q, x2), -2.13374055278905e-04f);
    q = __fadd_rn(__fmul_rn(q, x2), -1.68282697438203e-03f);
    q = __fadd_rn(__fmul_rn(q, x2), -7.37332916720468e-03f);
    q = __fadd_rn(__fmul_rn(q, x2), -1.42647390514189e-02f);
    return __fdiv_rn(p, q);
}

__device__ __forceinline__ float gelu_exact(float v) {
    const float t = __fdiv_rn(v, 1.41421356237309504880f);
    const float e = erf_xla(t);
    return 0.5f * __fmul_rn(v, __fadd_rn(e, 1.0f));
}

// Image-only fast path (k4): same poly, fast division (MUFU.RCP).
__device__ __forceinline__ float erf_fast(float x) {
    const float w  = fminf(fmaxf(x, -4.0f), 4.0f);
    const float x2 = w * w;
    float p = -2.72614225801306e-10f;
    p = fmaf(p, x2,  2.77068142495902e-08f);
    p = fmaf(p, x2, -2.10102402082508e-06f);
    p = fmaf(p, x2, -5.69250639462346e-05f);
    p = fmaf(p, x2, -7.34990630326855e-04f);
    p = fmaf(p, x2, -2.95459980854025e-03f);
    p = fmaf(p, x2, -1.60960333262415e-02f);
    p = w * p;
    float q = -1.45660718464996e-05f;
    q = fmaf(q, x2, -2.13374055278905e-04f);
    q = fmaf(q, x2, -1.68282697438203e-03f);
    q = fmaf(q, x2, -7.37332916720468e-03f);
    q = fmaf(q, x2, -1.42647390514189e-02f);
    return __fdividef(p, q);
}

__device__ __forceinline__ float gelu_fast(float v) {
    const float t = v * 0.70710678118654752440f;
    return 0.5f * v * (1.0f + erf_fast(t));
}

__device__ __forceinline__ ull pk2(float lo, float hi) {
    ull r; asm("mov.b64 %0, {%1, %2};" : "=l"(r) : "f"(lo), "f"(hi)); return r;
}
__device__ __forceinline__ void upk2(ull v, float& lo, float& hi) {
    asm("mov.b64 {%0, %1}, %2;" : "=f"(lo), "=f"(hi) : "l"(v));
}
__device__ __forceinline__ ull fma2(ull a, ull b, ull c) {
    ull r; asm("fma.rn.f32x2 %0, %1, %2, %3;" : "=l"(r) : "l"(a), "l"(b), "l"(c));
    return r;
}
__device__ __forceinline__ ull add2(ull a, ull b) {
    ull r; asm("add.rn.f32x2 %0, %1, %2;" : "=l"(r) : "l"(a), "l"(b));
    return r;
}

// ---------------------------------------------------------------------------
// K1: conv1 (1->16) + bias-after + maxpool2 + gelu (EXACT chains). (R13 form)
// ---------------------------------------------------------------------------
__global__ void k1_conv1_pool_gelu(const float* __restrict__ x,
                                   const float* __restrict__ w1,
                                   const float* __restrict__ b1,
                                   float* __restrict__ h1) {
    __shared__ float xs[34][35];
    __shared__ __align__(8) float wsT[9 * 16];   // [j][oc]
    __shared__ float bs[16];

    const int b   = blockIdx.z;
    const int px0 = blockIdx.x * 16, py0 = blockIdx.y * 16;
    const int ty = threadIdx.y, tx = threadIdx.x;
    const int t  = ty * 16 + tx;

    if (t < 144) { const int j = t >> 4, o = t & 15; wsT[j * 16 + o] = w1[o * 9 + j]; }
    if (t < 16)  bs[t] = b1[t];

    const float* xb = x + (size_t)b * 65536;
    for (int i = t; i < 34 * 34; i += 256) {
        int r = i / 34, c = i % 34;
        int gy = 2 * py0 - 1 + r, gx = 2 * px0 - 1 + c;
        float v = 0.0f;
        if (gy >= 0 && gy < 256 && gx >= 0 && gx < 256) v = xb[gy * 256 + gx];
        xs[r][c] = v;
    }
    __syncthreads();

    ull xin[16];
    #pragma unroll
    for (int r = 0; r < 4; r++)
        #pragma unroll
        for (int c = 0; c < 4; c++) {
            const float v = xs[2 * ty + r][2 * tx + c];
            xin[r * 4 + c] = pk2(v, v);
        }

    #pragma unroll
    for (int h = 0; h < 2; h++) {
        ull acc[4][4];
        #pragma unroll
        for (int pos = 0; pos < 4; pos++)
            #pragma unroll
            for (int p = 0; p < 4; p++) acc[pos][p] = 0;

        #pragma unroll
        for (int j = 0; j < 9; j++) {
            const int ky = j / 3, kx = j % 3;
            const ull* wr = (const ull*)(wsT + j * 16) + h * 4;
            #pragma unroll
            for (int p = 0; p < 4; p++) {
                const ull wv = wr[p];
                acc[0][p] = fma2(wv, xin[(0 + ky) * 4 + (0 + kx)], acc[0][p]);
                acc[1][p] = fma2(wv, xin[(0 + ky) * 4 + (1 + kx)], acc[1][p]);
                acc[2][p] = fma2(wv, xin[(1 + ky) * 4 + (0 + kx)], acc[2][p]);
                acc[3][p] = fma2(wv, xin[(1 + ky) * 4 + (1 + kx)], acc[3][p]);
            }
        }

        #pragma unroll
        for (int p = 0; p < 4; p++) {
            float a0[4], a1[4];
            #pragma unroll
            for (int pos = 0; pos < 4; pos++) upk2(acc[pos][p], a0[pos], a1[pos]);
            const int oc0 = h * 8 + 2 * p, oc1 = oc0 + 1;
            const float bb0 = bs[oc0], bb1 = bs[oc1];
            const float m0 = fmaxf(fmaxf(__fadd_rn(a0[0], bb0), __fadd_rn(a0[1], bb0)),
                                   fmaxf(__fadd_rn(a0[2], bb0), __fadd_rn(a0[3], bb0)));
            const float m1 = fmaxf(fmaxf(__fadd_rn(a1[0], bb1), __fadd_rn(a1[1], bb1)),
                                   fmaxf(__fadd_rn(a1[2], bb1), __fadd_rn(a1[3], bb1)));
            h1[(((size_t)b * 16 + oc0) * 128 + (py0 + ty)) * 128 + (px0 + tx)] = gelu_exact(m0);
            h1[(((size_t)b * 16 + oc1) * 128 + (py0 + ty)) * 128 + (px0 + tx)] = gelu_exact(m1);
        }
    }
}

// ---------------------------------------------------------------------------
// K2: conv2 (16->32), EXACT per-oc chain over (ky,kx,ic) ic-innermost. (R13)
// ---------------------------------------------------------------------------
__global__ void k2_conv2_pool(const float* __restrict__ h1,
                              const float* __restrict__ w2,
                              const float* __restrict__ b2,
                              float* __restrict__ h2) {
    __shared__ float hs[16][18][18];                 // 20736 B
    __shared__ __align__(8) float wsT[144 * 32];     // 18432 B, [j][oc]
    __shared__ float bs[32];

    const int b   = blockIdx.z;
    const int px0 = blockIdx.x * 8, py0 = blockIdx.y * 8;
    const int t   = threadIdx.x;

    for (int i = t; i < 4608; i += 256) {
        int o = i & 31, j = i >> 5;
        wsT[j * 32 + o] = w2[o * 144 + j];
    }
    if (t < 32) bs[t] = b2[t];

    const float* hb = h1 + (size_t)b * 16 * 16384;
    for (int i = t; i < 16 * 18 * 18; i += 256) {
        int ic = i / 324, rem = i % 324;
        int r = rem / 18, c = rem % 18;
        int gy = 2 * py0 - 1 + r, gx = 2 * px0 - 1 + c;
        float v = 0.0f;
        if (gy >= 0 && gy < 128 && gx >= 0 && gx < 128) v = hb[ic * 16384 + gy * 128 + gx];
        hs[ic][r][c] = v;
    }
    __syncthreads();

    const int s  = t & 63, g = t >> 6;
    const int px = s & 7, py = s >> 3;

    ull acc[4][4];
    #pragma unroll
    for (int p = 0; p < 4; p++)
        #pragma unroll
        for (int wv = 0; wv < 4; wv++) acc[p][wv] = 0;

    #pragma unroll
    for (int ky = 0; ky < 3; ky++)
    #pragma unroll
    for (int kx = 0; kx < 3; kx++) {
        for (int ic = 0; ic < 16; ic++) {          // ic innermost (exact order)
            const float u00 = hs[ic][2 * py + 0 + ky][2 * px + 0 + kx];
            const float u01 = hs[ic][2 * py + 0 + ky][2 * px + 1 + kx];
            const float u10 = hs[ic][2 * py + 1 + ky][2 * px + 0 + kx];
            const float u11 = hs[ic][2 * py + 1 + ky][2 * px + 1 + kx];
            const ull s00 = pk2(u00, u00), s01 = pk2(u01, u01);
            const ull s10 = pk2(u10, u10), s11 = pk2(u11, u11);
            const int j = ic * 9 + ky * 3 + kx;
            const ull* wrow = (const ull*)(wsT + j * 32) + g * 4;
            #pragma unroll
            for (int p = 0; p < 4; p++) {
                const ull wp = wrow[p];
                acc[p][0] = fma2(wp, s00, acc[p][0]);
                acc[p][1] = fma2(wp, s01, acc[p][1]);
                acc[p][2] = fma2(wp, s10, acc[p][2]);
                acc[p][3] = fma2(wp, s11, acc[p][3]);
            }
        }
    }

    #pragma unroll
    for (int p = 0; p < 4; p++) {
        float a0[4], a1[4];
        #pragma unroll
        for (int wv = 0; wv < 4; wv++) upk2(acc[p][wv], a0[wv], a1[wv]);
        const int oc0 = g * 8 + 2 * p, oc1 = oc0 + 1;
        const float bb0 = bs[oc0], bb1 = bs[oc1];
        float m0 = fmaxf(fmaxf(__fadd_rn(a0[0], bb0), __fadd_rn(a0[1], bb0)),
                         fmaxf(__fadd_rn(a0[2], bb0), __fadd_rn(a0[3], bb0)));
        float m1 = fmaxf(fmaxf(__fadd_rn(a1[0], bb1), __fadd_rn(a1[1], bb1)),
                         fmaxf(__fadd_rn(a1[2], bb1), __fadd_rn(a1[3], bb1)));
        h2[(((size_t)b * 32 + oc0) * 64 + (py0 + py)) * 64 + (px0 + px)] = m0;
        h2[(((size_t)b * 32 + oc1) * 64 + (py0 + py)) * 64 + (px0 + px)] = m1;
    }
}

// ---------------------------------------------------------------------------
// K3: VQ (EXACT values). 2 vectors/thread; 16-k inner blocks (halves pk2
// recompute); packed scoring: dist = fma2(-2,xc,x2) + c2 per lane ==
// fl(fl(x2 - 2*xc) + c2) bitwise (2*xc exact). First-min scan in k order.
// grid 512, block 256, dyn smem 67584 B.
// ---------------------------------------------------------------------------
__global__ void __launch_bounds__(256, 2)
k3_vq(const float* __restrict__ h2,
      const float* __restrict__ cb,
      float* __restrict__ q,
      float* __restrict__ outF,
      float* __restrict__ partial) {
    extern __shared__ __align__(16) float sm[];
    float* scbT = sm;             // [32][512]
    float* sc2  = sm + 32 * 512;  // [512]
    const int t = threadIdx.x;

    for (int i = t; i < 32 * 512; i += 256) {
        int d = i >> 9, k = i & 511;
        scbT[i] = cb[k * 32 + d];
    }
    for (int k = t; k < 512; k += 256) {
        const float* c = cb + k * 32;
        float s = 0.0f;
        #pragma unroll
        for (int d = 0; d < 32; d++) s = __fadd_rn(s, __fmul_rn(c[d], c[d]));
        sc2[k] = s;
    }
    __syncthreads();

    const int vA = blockIdx.x * 256 + t;        // [0, 131072)
    const int vB = vA + 131072;
    const int bA = vA >> 12, pA = vA & 4095;
    const int bB = vB >> 12, pB = vB & 4095;
    const float* hA = h2 + ((size_t)bA * 32) * 4096 + pA;
    const float* hB = h2 + ((size_t)bB * 32) * 4096 + pB;

    float xvA[32], xvB[32];
    float x2A = 0.0f, x2B = 0.0f;
    #pragma unroll
    for (int d = 0; d < 32; d++) {
        xvA[d] = hA[(size_t)d * 4096];
        xvB[d] = hB[(size_t)d * 4096];
        x2A = __fadd_rn(x2A, __fmul_rn(xvA[d], xvA[d]));
        x2B = __fadd_rn(x2B, __fmul_rn(xvB[d], xvB[d]));
    }

    const ull x2Ap = pk2(x2A, x2A);
    const ull x2Bp = pk2(x2B, x2B);
    const ull neg2 = pk2(-2.0f, -2.0f);

    float bestA = 3.4e38f, bestB = 3.4e38f;
    int biA = 0, biB = 0;
    for (int k0 = 0; k0 < 512; k0 += 16) {
        ull aA[8], aB[8];
        #pragma unroll
        for (int j = 0; j < 8; j++) { aA[j] = 0; aB[j] = 0; }
        #pragma unroll
        for (int d = 0; d < 32; d++) {
            const ull* row = (const ull*)(scbT + d * 512 + k0);
            const ull xa = pk2(xvA[d], xvA[d]);
            const ull xb = pk2(xvB[d], xvB[d]);
            #pragma unroll
            for (int j = 0; j < 8; j++) {
                const ull r = row[j];
                aA[j] = fma2(r, xa, aA[j]);
                aB[j] = fma2(r, xb, aB[j]);
            }
        }
        const ull* c2p = (const ull*)(sc2 + k0);
        #pragma unroll
        for (int j = 0; j < 8; j++) {
            const ull c2 = c2p[j];
            // per lane: fl(fma(-2,xc,x2)) == fl(x2 - fl(2*xc)); then +c2.
            const ull dA2 = add2(fma2(neg2, aA[j], x2Ap), c2);
            const ull dB2 = add2(fma2(neg2, aB[j], x2Bp), c2);
            float dA0, dA1, dB0, dB1;
            upk2(dA2, dA0, dA1);
            upk2(dB2, dB0, dB1);
            const int kk = k0 + 2 * j;
            if (dA0 < bestA) { bestA = dA0; biA = kk; }
            if (dA1 < bestA) { bestA = dA1; biA = kk + 1; }
            if (dB0 < bestB) { bestB = dB0; biB = kk; }
            if (dB1 < bestB) { bestB = dB1; biB = kk + 1; }
        }
    }

    float err = 0.0f;
    {
        const float* c = cb + biA * 32;
        float* qb = q + ((size_t)bA * 32) * 4096 + pA;
        #pragma unroll
        for (int d = 0; d < 32; d++) {
            const float e = __fsub_rn(c[d], xvA[d]);
            err = __fadd_rn(err, __fmul_rn(e, e));
            qb[(size_t)d * 4096] = __fadd_rn(xvA[d], e);
        }
        outF[4194304 + vA] = (float)biA;
    }
    {
        const float* c = cb + biB * 32;
        float* qb = q + ((size_t)bB * 32) * 4096 + pB;
        #pragma unroll
        for (int d = 0; d < 32; d++) {
            const float e = __fsub_rn(c[d], xvB[d]);
            err = __fadd_rn(err, __fmul_rn(e, e));
            qb[(size_t)d * 4096] = __fadd_rn(xvB[d], e);
        }
        outF[4194304 + vB] = (float)biB;
    }

    __shared__ float red[256];
    red[t] = err;
    __syncthreads();
    #pragma unroll
    for (int s2 = 128; s2 > 0; s2 >>= 1) {
        if (t < s2) red[t] += red[t + s2];
        __syncthreads();
    }
    if (t == 0) partial[blockIdx.x] = red[0];
}

// ---------------------------------------------------------------------------
// K4: upsample2 + conv3 + bias + gelu, PHASE-DECOMPOSED (image path).
// cw [ph][tap][c][oc16], LDS.64 weight broadcasts. 2 ADJACENT px/thread:
// windows overlap one column -> 6 act LDS + 6 pk2 per c (was 8+8).
// Tile 32x16 out, grid (4,8,B), dyn smem 55872 B.
// ---------------------------------------------------------------------------
__global__ void k4_up_conv3_gelu(const float* __restrict__ q,
                                 const float* __restrict__ w3,
                                 const float* __restrict__ b3,
                                 float* __restrict__ h3) {
    extern __shared__ __align__(16) float sm4[];
    float* qs = sm4;                 // 5760 floats (q tile [32][10][18]); temp for raw w3
    float* cw = sm4 + 5760;          // 8192 floats: [ph][tap][c][oc16]
    float* bs = sm4 + 13952;         // 16

    const int b   = blockIdx.z;
    const int ox0 = blockIdx.x * 32, oy0 = blockIdx.y * 16;
    const int t   = threadIdx.x;

    for (int i = t; i < 4608; i += 256) qs[i] = w3[i];
    if (t < 16) bs[t] = b3[t];
    __syncthreads();

    for (int e = t; e < 8192; e += 256) {
        const int o = e & 15, c = (e >> 4) & 31, tap = (e >> 9) & 3, ph = e >> 11;
        const int tx = tap & 1, ty = tap >> 1, dx = ph & 1, dy = ph >> 1;
        const int ys = dy ? (ty ? 2 : 0) : (ty ? 1 : 0);
        const int yc = dy ? (ty ? 1 : 2) : (ty ? 2 : 1);
        const int xs = dx ? (tx ? 2 : 0) : (tx ? 1 : 0);
        const int xc = dx ? (tx ? 1 : 2) : (tx ? 2 : 1);
        float ssum = 0.0f;
        for (int iy = 0; iy < yc; iy++)
            for (int ix = 0; ix < xc; ix++)
                ssum += qs[o * 288 + c * 9 + (ys + iy) * 3 + (xs + ix)];
        cw[e] = ssum;
    }
    __syncthreads();

    const int qyb = (oy0 >> 1) - 1, qxb = (ox0 >> 1) - 1;
    const float* qb_ = q + (size_t)b * 131072;
    for (int i = t; i < 5760; i += 256) {
        const int c = i / 180, rem = i % 180, r = rem / 18, cc = rem % 18;
        const int gy = qyb + r, gx = qxb + cc;
        float v = 0.0f;
        if (gy >= 0 && gy < 64 && gx >= 0 && gx < 64) v = qb_[c * 4096 + gy * 64 + gx];
        qs[c * 180 + r * 18 + cc] = v;
    }
    __syncthreads();

    const int wrp = t >> 5, lane = t & 31;
    const int dx = wrp & 1, dy = (wrp >> 1) & 1, sub = wrp >> 2;
    const int ph = dy * 2 + dx;
    // 64 threads per phase, each handles ADJACENT u columns (2m, 2m+1).
    const int idx = sub * 32 + lane;            // [0,64)
    const int uxA = 2 * (idx & 7), uyA = idx >> 3;   // u grid 16x8
    const int uxB = uxA + 1;
    const int jxA = uxA + dx, jyA = uyA + dy;   // jxB = jxA + 1

    ull A[8], B[8];
    #pragma unroll
    for (int p = 0; p < 8; p++) { A[p] = 0; B[p] = 0; }

    const float* cwp = cw + ph * 2048;
    for (int c = 0; c < 32; c++) {
        const float* qc = qs + c * 180;
        const float v00 = qc[jyA * 18 + jxA];
        const float v01 = qc[jyA * 18 + jxA + 1];
        const float v02 = qc[jyA * 18 + jxA + 2];
        const float v10 = qc[(jyA + 1) * 18 + jxA];
        const float v11 = qc[(jyA + 1) * 18 + jxA + 1];
        const float v12 = qc[(jyA + 1) * 18 + jxA + 2];
        const ull p00 = pk2(v00, v00), p01 = pk2(v01, v01), p02 = pk2(v02, v02);
        const ull p10 = pk2(v10, v10), p11 = pk2(v11, v11), p12 = pk2(v12, v12);
        const ull sa[4] = { p00, p01, p10, p11 };
        const ull sb[4] = { p01, p02, p11, p12 };
        #pragma unroll
        for (int tap = 0; tap < 4; tap++) {
            const ull* wr = (const ull*)(cwp + (tap * 32 + c) * 16);
            #pragma unroll
            for (int p = 0; p < 8; p++) {
                const ull wv = wr[p];
                A[p] = fma2(wv, sa[tap], A[p]);
                B[p] = fma2(wv, sb[tap], B[p]);
            }
        }
    }

    const int oxA = ox0 + 2 * uxA + dx, oyA = oy0 + 2 * uyA + dy;
    const int oxB = oxA + 2;   // uxB = uxA+1 -> +2 in output x
    #pragma unroll
    for (int p = 0; p < 8; p++) {
        float a0, a1, c0, c1;
        upk2(A[p], a0, a1);
        upk2(B[p], c0, c1);
        h3[(((size_t)b * 16 + 2 * p + 0) * 128 + oyA) * 128 + oxA] = gelu_fast(a0 + bs[2 * p + 0]);
        h3[(((size_t)b * 16 + 2 * p + 1) * 128 + oyA) * 128 + oxA] = gelu_fast(a1 + bs[2 * p + 1]);
        h3[(((size_t)b * 16 + 2 * p + 0) * 128 + oyA) * 128 + oxB] = gelu_fast(c0 + bs[2 * p + 0]);
        h3[(((size_t)b * 16 + 2 * p + 1) * 128 + oyA) * 128 + oxB] = gelu_fast(c1 + bs[2 * p + 1]);
    }
}

// ---------------------------------------------------------------------------
// K5: upsample2 + conv4 (16->1) + clip, PHASE-DECOMPOSED (image path). (R13)
// ---------------------------------------------------------------------------
__global__ void k5_up_conv4_clip(const float* __restrict__ h3,
                                 const float* __restrict__ w4,
                                 const float* __restrict__ b4,
                                 float* __restrict__ outF) {
    __shared__ float hs[16 * 18 * 18];
    __shared__ float cw5[256];
    __shared__ float wtmp[144];

    const int b   = blockIdx.z;
    const int ox0 = blockIdx.x * 32, oy0 = blockIdx.y * 32;
    const int t   = threadIdx.x;

    if (t < 144) wtmp[t] = w4[t];
    __syncthreads();

    {
        const int c = t & 15, tap = (t >> 4) & 3, ph = t >> 6;
        const int tx = tap & 1, ty = tap >> 1, dx = ph & 1, dy = ph >> 1;
        const int ys = dy ? (ty ? 2 : 0) : (ty ? 1 : 0);
        const int yc = dy ? (ty ? 1 : 2) : (ty ? 2 : 1);
        const int xs = dx ? (tx ? 2 : 0) : (tx ? 1 : 0);
        const int xc = dx ? (tx ? 1 : 2) : (tx ? 2 : 1);
        float ssum = 0.0f;
        for (int iy = 0; iy < yc; iy++)
            for (int ix = 0; ix < xc; ix++)
                ssum += wtmp[c * 9 + (ys + iy) * 3 + (xs + ix)];
        cw5[t] = ssum;
    }

    const int qyb = (oy0 >> 1) - 1, qxb = (ox0 >> 1) - 1;
    const float* hb = h3 + (size_t)b * 16 * 16384;
    for (int i = t; i < 16 * 324; i += 256) {
        const int c = i / 324, rem = i % 324, r = rem / 18, cc = rem % 18;
        const int gy = qyb + r, gx = qxb + cc;
        float v = 0.0f;
        if (gy >= 0 && gy < 128 && gx >= 0 && gx < 128) v = hb[c * 16384 + gy * 128 + gx];
        hs[c * 324 + r * 18 + cc] = v;
    }
    __syncthreads();

    const int wrp = t >> 5, lane = t & 31;
    const int dx = wrp & 1, dy = (wrp >> 1) & 1, sub = wrp >> 2;
    const float* cwp = cw5 + (dy * 2 + dx) * 64;
    const float bias = b4[0];

    int jx[4], jy[4], ox[4], oy[4];
    #pragma unroll
    for (int i = 0; i < 4; i++) {
        const int idx = sub * 32 + lane + 64 * i;
        const int ux = idx & 15, uy = idx >> 4;
        jx[i] = ux + dx; jy[i] = uy + dy;
        ox[i] = ox0 + 2 * ux + dx; oy[i] = oy0 + 2 * uy + dy;
    }

    float acc[4] = {0.f, 0.f, 0.f, 0.f};
    for (int c = 0; c < 16; c++) {
        const float w00 = cwp[c], w01 = cwp[16 + c], w10 = cwp[32 + c], w11 = cwp[48 + c];
        const float* hc = hs + c * 324;
        #pragma unroll
        for (int i = 0; i < 4; i++) {
            acc[i] = fmaf(hc[jy[i] * 18 + jx[i]],           w00, acc[i]);
            acc[i] = fmaf(hc[jy[i] * 18 + jx[i] + 1],       w01, acc[i]);
            acc[i] = fmaf(hc[(jy[i] + 1) * 18 + jx[i]],     w10, acc[i]);
            acc[i] = fmaf(hc[(jy[i] + 1) * 18 + jx[i] + 1], w11, acc[i]);
        }
    }

    #pragma unroll
    for (int i = 0; i < 4; i++) {
        float a = acc[i] + bias;
        a = fminf(fmaxf(a, -1.0f), 1.0f);
        outF[(size_t)b * 65536 + oy[i] * 256 + ox[i]] = a;
    }
}

// ---------------------------------------------------------------------------
// K6: deterministic final reduction of commit loss (512 partials).
// ---------------------------------------------------------------------------
__global__ void k6_loss(const float* __restrict__ partial, float* __restrict__ outF) {
    __shared__ float red[256];
    const int t = threadIdx.x;
    red[t] = partial[t] + partial[t + 256];
    __syncthreads();
    #pragma unroll
    for (int s2 = 128; s2 > 0; s2 >>= 1) {
        if (t < s2) red[t] += red[t + s2];
        __syncthreads();
    }
    if (t == 0) outF[4194304 + 262144] = red[0] * (1.0f / 8388608.0f);
}

// ---------------------------------------------------------------------------
extern "C" void kernel_launch(void* const* d_in, const int* in_sizes, int n_in,
                              void* d_out, int out_size) {
    const float* x  = (const float*)d_in[0];
    const float* w1 = (const float*)d_in[1];
    const float* b1 = (const float*)d_in[2];
    const float* w2 = (const float*)d_in[3];
    const float* b2 = (const float*)d_in[4];
    const float* cb = (const float*)d_in[5];
    const float* w3 = (const float*)d_in[6];
    const float* b3 = (const float*)d_in[7];
    const float* w4 = (const float*)d_in[8];
    const float* b4 = (const float*)d_in[9];
    float* outF = (float*)d_out;

    float *h1, *h2, *q, *h3, *partial;
    cudaGetSymbolAddress((void**)&h1, g_h1);
    cudaGetSymbolAddress((void**)&h2, g_h2);
    cudaGetSymbolAddress((void**)&q,  g_q);
    cudaGetSymbolAddress((void**)&h3, g_h3);
    cudaGetSymbolAddress((void**)&partial, g_partial);

    cudaFuncSetAttribute(k3_vq,            cudaFuncAttributeMaxDynamicSharedMemorySize, 67584);
    cudaFuncSetAttribute(k4_up_conv3_gelu, cudaFuncAttributeMaxDynamicSharedMemorySize, 55872);

    k1_conv1_pool_gelu<<<dim3(8, 8, BATCH), dim3(16, 16)>>>(x, w1, b1, h1);
    k2_conv2_pool<<<dim3(8, 8, BATCH), 256>>>(h1, w2, b2, h2);
    k3_vq<<<512, 256, 67584>>>(h2, cb, q, outF, partial);
    k4_up_conv3_gelu<<<dim3(4, 8, BATCH), 256, 55872>>>(q, w3, b3, h3);
    k5_up_conv4_clip<<<dim3(8, 8, BATCH), 256>>>(h3, w4, b4, outF);
    k6_loss<<<1, 256>>>(partial, outF);
}

// round 15
// speedup vs baseline: 1.2262x; 1.0166x over previous
#include <cuda_runtime.h>
#include <math.h>

// ---------------------------------------------------------------------------
// SimpleVQAutoEncoder forward. k1/k2/k3 bit-exact (XLA-CPU-aligned, decide VQ
// indices); k4/k5 image-only -> re-associated (phase-decomposed).
// R15 = R14 (864us best) + bank-conflict fixes (odd strides + parity xor
// swizzle; layout-only) + packed k1 gelu poly (per-lane bit-exact) + packed
// k4 bias add. Rules: LDS.64 broadcasts only; keep occupancy; chains locked.
// Outputs in d_out (fp32): image | indices | commit_loss
// ---------------------------------------------------------------------------

#define BATCH 64
typedef unsigned long long ull;

__device__ float g_h1[BATCH * 16 * 128 * 128];
__device__ float g_h2[BATCH * 32 * 64 * 64];
__device__ float g_q [BATCH * 32 * 64 * 64];
__device__ float g_h3[BATCH * 16 * 128 * 128];
__device__ float g_partial[1024];

__device__ __forceinline__ ull pk2(float lo, float hi) {
    ull r; asm("mov.b64 %0, {%1, %2};" : "=l"(r) : "f"(lo), "f"(hi)); return r;
}
__device__ __forceinline__ void upk2(ull v, float& lo, float& hi) {
    asm("mov.b64 {%0, %1}, %2;" : "=f"(lo), "=f"(hi) : "l"(v));
}
__device__ __forceinline__ ull fma2(ull a, ull b, ull c) {
    ull r; asm("fma.rn.f32x2 %0, %1, %2, %3;" : "=l"(r) : "l"(a), "l"(b), "l"(c));
    return r;
}
__device__ __forceinline__ ull add2(ull a, ull b) {
    ull r; asm("add.rn.f32x2 %0, %1, %2;" : "=l"(r) : "l"(a), "l"(b));
    return r;
}
__device__ __forceinline__ ull mul2(ull a, ull b) {
    ull r; asm("mul.rn.f32x2 %0, %1, %2;" : "=l"(r) : "l"(a), "l"(b));
    return r;
}

// XLA f32 erf: single rational approximation, clamp to [-4,4]. (exact path)
__device__ __forceinline__ float erf_xla(float x) {
    const float w  = fminf(fmaxf(x, -4.0f), 4.0f);
    const float x2 = __fmul_rn(w, w);
    float p = -2.72614225801306e-10f;
    p = __fadd_rn(__fmul_rn(p, x2),  2.77068142495902e-08f);
    p = __fadd_rn(__fmul_rn(p, x2), -2.10102402082508e-06f);
    p = __fadd_rn(__fmul_rn(p, x2), -5.69250639462346e-05f);
    p = __fadd_rn(__fmul_rn(p, x2), -7.34990630326855e-04f);
    p = __fadd_rn(__fmul_rn(p, x2), -2.95459980854025e-03f);
    p = __fadd_rn(__fmul_rn(p, x2), -1.60960333262415e-02f);
    p = __fmul_rn(w, p);
    float q = -1.45660718464996e-05f;
    q = __fadd_rn(__fmul_rn(q, x2), -2.13374055278905e-04f);
    q = __fadd_rn(__fmul_rn(q, x2), -1.68282697438203e-03f);
    q = __fadd_rn(__fmul_rn(q, x2), -7.37332916720468e-03f);
    q = __fadd_rn(__fmul_rn(q, x2), -1.42647390514189e-02f);
    return __fdiv_rn(p, q);
}

__device__ __forceinline__ float gelu_exact(float v) {
    const float t = __fdiv_rn(v, 1.41421356237309504880f);
    const float e = erf_xla(t);
    return 0.5f * __fmul_rn(v, __fadd_rn(e, 1.0f));
}

// Packed-pair EXACT gelu: per-lane ops identical to gelu_exact (mul.rn/add.rn
// Horner, scalar IEEE divs, scalar clamps) -> bitwise same results.
__device__ __forceinline__ void gelu2_exact(float v0, float v1, float& g0, float& g1) {
    const float t0 = __fdiv_rn(v0, 1.41421356237309504880f);
    const float t1 = __fdiv_rn(v1, 1.41421356237309504880f);
    const float w0 = fminf(fmaxf(t0, -4.0f), 4.0f);
    const float w1 = fminf(fmaxf(t1, -4.0f), 4.0f);
    const ull w = pk2(w0, w1);
    const ull s = mul2(w, w);
    ull p = pk2(-2.72614225801306e-10f, -2.72614225801306e-10f);
    p = add2(mul2(p, s), pk2( 2.77068142495902e-08f,  2.77068142495902e-08f));
    p = add2(mul2(p, s), pk2(-2.10102402082508e-06f, -2.10102402082508e-06f));
    p = add2(mul2(p, s), pk2(-5.69250639462346e-05f, -5.69250639462346e-05f));
    p = add2(mul2(p, s), pk2(-7.34990630326855e-04f, -7.34990630326855e-04f));
    p = add2(mul2(p, s), pk2(-2.95459980854025e-03f, -2.95459980854025e-03f));
    p = add2(mul2(p, s), pk2(-1.60960333262415e-02f, -1.60960333262415e-02f));
    p = mul2(w, p);
    ull q = pk2(-1.45660718464996e-05f, -1.45660718464996e-05f);
    q = add2(mul2(q, s), pk2(-2.13374055278905e-04f, -2.13374055278905e-04f));
    q = add2(mul2(q, s), pk2(-1.68282697438203e-03f, -1.68282697438203e-03f));
    q = add2(mul2(q, s), pk2(-7.37332916720468e-03f, -7.37332916720468e-03f));
    q = add2(mul2(q, s), pk2(-1.42647390514189e-02f, -1.42647390514189e-02f));
    float p0, p1, q0, q1;
    upk2(p, p0, p1);
    upk2(q, q0, q1);
    const float e0 = __fdiv_rn(p0, q0);
    const float e1 = __fdiv_rn(p1, q1);
    g0 = 0.5f * __fmul_rn(v0, __fadd_rn(e0, 1.0f));
    g1 = 0.5f * __fmul_rn(v1, __fadd_rn(e1, 1.0f));
}

// Image-only fast path (k4): same poly, fast division (MUFU.RCP).
__device__ __forceinline__ float erf_fast(float x) {
    const float w  = fminf(fmaxf(x, -4.0f), 4.0f);
    const float x2 = w * w;
    float p = -2.72614225801306e-10f;
    p = fmaf(p, x2,  2.77068142495902e-08f);
    p = fmaf(p, x2, -2.10102402082508e-06f);
    p = fmaf(p, x2, -5.69250639462346e-05f);
    p = fmaf(p, x2, -7.34990630326855e-04f);
    p = fmaf(p, x2, -2.95459980854025e-03f);
    p = fmaf(p, x2, -1.60960333262415e-02f);
    p = w * p;
    float q = -1.45660718464996e-05f;
    q = fmaf(q, x2, -2.13374055278905e-04f);
    q = fmaf(q, x2, -1.68282697438203e-03f);
    q = fmaf(q, x2, -7.37332916720468e-03f);
    q = fmaf(q, x2, -1.42647390514189e-02f);
    return __fdividef(p, q);
}

__device__ __forceinline__ float gelu_fast(float v) {
    const float t = v * 0.70710678118654752440f;
    return 0.5f * v * (1.0f + erf_fast(t));
}

// ---------------------------------------------------------------------------
// K1: conv1 (1->16) + bias-after + maxpool2 + gelu (EXACT chains).
// xs: stride 36 + parity xor swizzle -> warp rows hit odd/even banks.
// Packed gelu pairs (bit-exact per lane).
// ---------------------------------------------------------------------------
#define XS(r, c) xs[(r) * 36 + ((c) ^ ((((r) >> 1)) & 1))]

__global__ void k1_conv1_pool_gelu(const float* __restrict__ x,
                                   const float* __restrict__ w1,
                                   const float* __restrict__ b1,
                                   float* __restrict__ h1) {
    __shared__ float xs[34 * 36];
    __shared__ __align__(8) float wsT[9 * 16];   // [j][oc]
    __shared__ float bs[16];

    const int b   = blockIdx.z;
    const int px0 = blockIdx.x * 16, py0 = blockIdx.y * 16;
    const int ty = threadIdx.y, tx = threadIdx.x;
    const int t  = ty * 16 + tx;

    if (t < 144) { const int j = t >> 4, o = t & 15; wsT[j * 16 + o] = w1[o * 9 + j]; }
    if (t < 16)  bs[t] = b1[t];

    const float* xb = x + (size_t)b * 65536;
    for (int i = t; i < 34 * 34; i += 256) {
        int r = i / 34, c = i % 34;
        int gy = 2 * py0 - 1 + r, gx = 2 * px0 - 1 + c;
        float v = 0.0f;
        if (gy >= 0 && gy < 256 && gx >= 0 && gx < 256) v = xb[gy * 256 + gx];
        XS(r, c) = v;
    }
    __syncthreads();

    ull xin[16];
    #pragma unroll
    for (int r = 0; r < 4; r++)
        #pragma unroll
        for (int c = 0; c < 4; c++) {
            const float v = XS(2 * ty + r, 2 * tx + c);
            xin[r * 4 + c] = pk2(v, v);
        }

    #pragma unroll
    for (int h = 0; h < 2; h++) {
        ull acc[4][4];
        #pragma unroll
        for (int pos = 0; pos < 4; pos++)
            #pragma unroll
            for (int p = 0; p < 4; p++) acc[pos][p] = 0;

        #pragma unroll
        for (int j = 0; j < 9; j++) {
            const int ky = j / 3, kx = j % 3;
            const ull* wr = (const ull*)(wsT + j * 16) + h * 4;
            #pragma unroll
            for (int p = 0; p < 4; p++) {
                const ull wv = wr[p];
                acc[0][p] = fma2(wv, xin[(0 + ky) * 4 + (0 + kx)], acc[0][p]);
                acc[1][p] = fma2(wv, xin[(0 + ky) * 4 + (1 + kx)], acc[1][p]);
                acc[2][p] = fma2(wv, xin[(1 + ky) * 4 + (0 + kx)], acc[2][p]);
                acc[3][p] = fma2(wv, xin[(1 + ky) * 4 + (1 + kx)], acc[3][p]);
            }
        }

        #pragma unroll
        for (int p = 0; p < 4; p++) {
            float a0[4], a1[4];
            #pragma unroll
            for (int pos = 0; pos < 4; pos++) upk2(acc[pos][p], a0[pos], a1[pos]);
            const int oc0 = h * 8 + 2 * p, oc1 = oc0 + 1;
            const float bb0 = bs[oc0], bb1 = bs[oc1];
            const float m0 = fmaxf(fmaxf(__fadd_rn(a0[0], bb0), __fadd_rn(a0[1], bb0)),
                                   fmaxf(__fadd_rn(a0[2], bb0), __fadd_rn(a0[3], bb0)));
            const float m1 = fmaxf(fmaxf(__fadd_rn(a1[0], bb1), __fadd_rn(a1[1], bb1)),
                                   fmaxf(__fadd_rn(a1[2], bb1), __fadd_rn(a1[3], bb1)));
            float g0, g1;
            gelu2_exact(m0, m1, g0, g1);
            h1[(((size_t)b * 16 + oc0) * 128 + (py0 + ty)) * 128 + (px0 + tx)] = g0;
            h1[(((size_t)b * 16 + oc1) * 128 + (py0 + ty)) * 128 + (px0 + tx)] = g1;
        }
    }
}

// ---------------------------------------------------------------------------
// K2: conv2 (16->32), EXACT per-oc chain over (ky,kx,ic) ic-innermost.
// hs: stride 19 + parity xor swizzle -> py-odd lanes on odd banks.
// ---------------------------------------------------------------------------
#define HS2(ic, r, c) hs[(ic) * 342 + (r) * 19 + ((c) ^ ((((r) >> 1)) & 1))]

__global__ void k2_conv2_pool(const float* __restrict__ h1,
                              const float* __restrict__ w2,
                              const float* __restrict__ b2,
                              float* __restrict__ h2) {
    __shared__ float hs[16 * 342];                   // 21888 B
    __shared__ __align__(8) float wsT[144 * 32];     // 18432 B, [j][oc]
    __shared__ float bs[32];

    const int b   = blockIdx.z;
    const int px0 = blockIdx.x * 8, py0 = blockIdx.y * 8;
    const int t   = threadIdx.x;

    for (int i = t; i < 4608; i += 256) {
        int o = i & 31, j = i >> 5;
        wsT[j * 32 + o] = w2[o * 144 + j];
    }
    if (t < 32) bs[t] = b2[t];

    const float* hb = h1 + (size_t)b * 16 * 16384;
    for (int i = t; i < 16 * 18 * 18; i += 256) {
        int ic = i / 324, rem = i % 324;
        int r = rem / 18, c = rem % 18;
        int gy = 2 * py0 - 1 + r, gx = 2 * px0 - 1 + c;
        float v = 0.0f;
        if (gy >= 0 && gy < 128 && gx >= 0 && gx < 128) v = hb[ic * 16384 + gy * 128 + gx];
        HS2(ic, r, c) = v;
    }
    __syncthreads();

    const int s  = t & 63, g = t >> 6;
    const int px = s & 7, py = s >> 3;

    ull acc[4][4];
    #pragma unroll
    for (int p = 0; p < 4; p++)
        #pragma unroll
        for (int wv = 0; wv < 4; wv++) acc[p][wv] = 0;

    #pragma unroll
    for (int ky = 0; ky < 3; ky++)
    #pragma unroll
    for (int kx = 0; kx < 3; kx++) {
        for (int ic = 0; ic < 16; ic++) {          // ic innermost (exact order)
            const float u00 = HS2(ic, 2 * py + 0 + ky, 2 * px + 0 + kx);
            const float u01 = HS2(ic, 2 * py + 0 + ky, 2 * px + 1 + kx);
            const float u10 = HS2(ic, 2 * py + 1 + ky, 2 * px + 0 + kx);
            const float u11 = HS2(ic, 2 * py + 1 + ky, 2 * px + 1 + kx);
            const ull s00 = pk2(u00, u00), s01 = pk2(u01, u01);
            const ull s10 = pk2(u10, u10), s11 = pk2(u11, u11);
            const int j = ic * 9 + ky * 3 + kx;
            const ull* wrow = (const ull*)(wsT + j * 32) + g * 4;
            #pragma unroll
            for (int p = 0; p < 4; p++) {
                const ull wp = wrow[p];
                acc[p][0] = fma2(wp, s00, acc[p][0]);
                acc[p][1] = fma2(wp, s01, acc[p][1]);
                acc[p][2] = fma2(wp, s10, acc[p][2]);
                acc[p][3] = fma2(wp, s11, acc[p][3]);
            }
        }
    }

    #pragma unroll
    for (int p = 0; p < 4; p++) {
        float a0[4], a1[4];
        #pragma unroll
        for (int wv = 0; wv < 4; wv++) upk2(acc[p][wv], a0[wv], a1[wv]);
        const int oc0 = g * 8 + 2 * p, oc1 = oc0 + 1;
        const float bb0 = bs[oc0], bb1 = bs[oc1];
        float m0 = fmaxf(fmaxf(__fadd_rn(a0[0], bb0), __fadd_rn(a0[1], bb0)),
                         fmaxf(__fadd_rn(a0[2], bb0), __fadd_rn(a0[3], bb0)));
        float m1 = fmaxf(fmaxf(__fadd_rn(a1[0], bb1), __fadd_rn(a1[1], bb1)),
                         fmaxf(__fadd_rn(a1[2], bb1), __fadd_rn(a1[3], bb1)));
        h2[(((size_t)b * 32 + oc0) * 64 + (py0 + py)) * 64 + (px0 + px)] = m0;
        h2[(((size_t)b * 32 + oc1) * 64 + (py0 + py)) * 64 + (px0 + px)] = m1;
    }
}

// ---------------------------------------------------------------------------
// K3: VQ (EXACT values). R14 form (unchanged).
// grid 512, block 256, dyn smem 67584 B.
// ---------------------------------------------------------------------------
__global__ void __launch_bounds__(256, 2)
k3_vq(const float* __restrict__ h2,
      const float* __restrict__ cb,
      float* __restrict__ q,
      float* __restrict__ outF,
      float* __restrict__ partial) {
    extern __shared__ __align__(16) float sm[];
    float* scbT = sm;             // [32][512]
    float* sc2  = sm + 32 * 512;  // [512]
    const int t = threadIdx.x;

    for (int i = t; i < 32 * 512; i += 256) {
        int d = i >> 9, k = i & 511;
        scbT[i] = cb[k * 32 + d];
    }
    for (int k = t; k < 512; k += 256) {
        const float* c = cb + k * 32;
        float s = 0.0f;
        #pragma unroll
        for (int d = 0; d < 32; d++) s = __fadd_rn(s, __fmul_rn(c[d], c[d]));
        sc2[k] = s;
    }
    __syncthreads();

    const int vA = blockIdx.x * 256 + t;        // [0, 131072)
    const int vB = vA + 131072;
    const int bA = vA >> 12, pA = vA & 4095;
    const int bB = vB >> 12, pB = vB & 4095;
    const float* hA = h2 + ((size_t)bA * 32) * 4096 + pA;
    const float* hB = h2 + ((size_t)bB * 32) * 4096 + pB;

    float xvA[32], xvB[32];
    float x2A = 0.0f, x2B = 0.0f;
    #pragma unroll
    for (int d = 0; d < 32; d++) {
        xvA[d] = hA[(size_t)d * 4096];
        xvB[d] = hB[(size_t)d * 4096];
        x2A = __fadd_rn(x2A, __fmul_rn(xvA[d], xvA[d]));
        x2B = __fadd_rn(x2B, __fmul_rn(xvB[d], xvB[d]));
    }

    const ull x2Ap = pk2(x2A, x2A);
    const ull x2Bp = pk2(x2B, x2B);
    const ull neg2 = pk2(-2.0f, -2.0f);

    float bestA = 3.4e38f, bestB = 3.4e38f;
    int biA = 0, biB = 0;
    for (int k0 = 0; k0 < 512; k0 += 16) {
        ull aA[8], aB[8];
        #pragma unroll
        for (int j = 0; j < 8; j++) { aA[j] = 0; aB[j] = 0; }
        #pragma unroll
        for (int d = 0; d < 32; d++) {
            const ull* row = (const ull*)(scbT + d * 512 + k0);
            const ull xa = pk2(xvA[d], xvA[d]);
            const ull xb = pk2(xvB[d], xvB[d]);
            #pragma unroll
            for (int j = 0; j < 8; j++) {
                const ull r = row[j];
                aA[j] = fma2(r, xa, aA[j]);
                aB[j] = fma2(r, xb, aB[j]);
            }
        }
        const ull* c2p = (const ull*)(sc2 + k0);
        #pragma unroll
        for (int j = 0; j < 8; j++) {
            const ull c2 = c2p[j];
            const ull dA2 = add2(fma2(neg2, aA[j], x2Ap), c2);
            const ull dB2 = add2(fma2(neg2, aB[j], x2Bp), c2);
            float dA0, dA1, dB0, dB1;
            upk2(dA2, dA0, dA1);
            upk2(dB2, dB0, dB1);
            const int kk = k0 + 2 * j;
            if (dA0 < bestA) { bestA = dA0; biA = kk; }
            if (dA1 < bestA) { bestA = dA1; biA = kk + 1; }
            if (dB0 < bestB) { bestB = dB0; biB = kk; }
            if (dB1 < bestB) { bestB = dB1; biB = kk + 1; }
        }
    }

    float err = 0.0f;
    {
        const float* c = cb + biA * 32;
        float* qb = q + ((size_t)bA * 32) * 4096 + pA;
        #pragma unroll
        for (int d = 0; d < 32; d++) {
            const float e = __fsub_rn(c[d], xvA[d]);
            err = __fadd_rn(err, __fmul_rn(e, e));
            qb[(size_t)d * 4096] = __fadd_rn(xvA[d], e);
        }
        outF[4194304 + vA] = (float)biA;
    }
    {
        const float* c = cb + biB * 32;
        float* qb = q + ((size_t)bB * 32) * 4096 + pB;
        #pragma unroll
        for (int d = 0; d < 32; d++) {
            const float e = __fsub_rn(c[d], xvB[d]);
            err = __fadd_rn(err, __fmul_rn(e, e));
            qb[(size_t)d * 4096] = __fadd_rn(xvB[d], e);
        }
        outF[4194304 + vB] = (float)biB;
    }

    __shared__ float red[256];
    red[t] = err;
    __syncthreads();
    #pragma unroll
    for (int s2 = 128; s2 > 0; s2 >>= 1) {
        if (t < s2) red[t] += red[t + s2];
        __syncthreads();
    }
    if (t == 0) partial[blockIdx.x] = red[0];
}

// ---------------------------------------------------------------------------
// K4: upsample2 + conv3 + bias + gelu, PHASE-DECOMPOSED (image path).
// qs stride 19 (odd -> rows alternate bank parity); packed bias add2.
// Tile 32x16 out, grid (4,8,B), dyn smem = (6080+8192+16)*4 = 57152 B.
// ---------------------------------------------------------------------------
__global__ void k4_up_conv3_gelu(const float* __restrict__ q,
                                 const float* __restrict__ w3,
                                 const float* __restrict__ b3,
                                 float* __restrict__ h3) {
    extern __shared__ __align__(16) float sm4[];
    float* qs = sm4;                 // 6080 floats (q tile [32][10][19]); temp for raw w3
    float* cw = sm4 + 6080;          // 8192 floats: [ph][tap][c][oc16]
    float* bs = sm4 + 14272;         // 16

    const int b   = blockIdx.z;
    const int ox0 = blockIdx.x * 32, oy0 = blockIdx.y * 16;
    const int t   = threadIdx.x;

    for (int i = t; i < 4608; i += 256) qs[i] = w3[i];
    if (t < 16) bs[t] = b3[t];
    __syncthreads();

    for (int e = t; e < 8192; e += 256) {
        const int o = e & 15, c = (e >> 4) & 31, tap = (e >> 9) & 3, ph = e >> 11;
        const int tx = tap & 1, ty = tap >> 1, dx = ph & 1, dy = ph >> 1;
        const int ys = dy ? (ty ? 2 : 0) : (ty ? 1 : 0);
        const int yc = dy ? (ty ? 1 : 2) : (ty ? 2 : 1);
        const int xs = dx ? (tx ? 2 : 0) : (tx ? 1 : 0);
        const int xc = dx ? (tx ? 1 : 2) : (tx ? 2 : 1);
        float ssum = 0.0f;
        for (int iy = 0; iy < yc; iy++)
            for (int ix = 0; ix < xc; ix++)
                ssum += qs[o * 288 + c * 9 + (ys + iy) * 3 + (xs + ix)];
        cw[e] = ssum;
    }
    __syncthreads();

    const int qyb = (oy0 >> 1) - 1, qxb = (ox0 >> 1) - 1;
    const float* qb_ = q + (size_t)b * 131072;
    for (int i = t; i < 5760; i += 256) {
        const int c = i / 180, rem = i % 180, r = rem / 18, cc = rem % 18;
        const int gy = qyb + r, gx = qxb + cc;
        float v = 0.0f;
        if (gy >= 0 && gy < 64 && gx >= 0 && gx < 64) v = qb_[c * 4096 + gy * 64 + gx];
        qs[c * 190 + r * 19 + cc] = v;
    }
    __syncthreads();

    const int wrp = t >> 5, lane = t & 31;
    const int dx = wrp & 1, dy = (wrp >> 1) & 1, sub = wrp >> 2;
    const int ph = dy * 2 + dx;
    const int idx = sub * 32 + lane;            // [0,64)
    const int uxA = 2 * (idx & 7), uyA = idx >> 3;   // u grid 16x8
    const int jxA = uxA + dx, jyA = uyA + dy;

    ull A[8], B[8];
    #pragma unroll
    for (int p = 0; p < 8; p++) { A[p] = 0; B[p] = 0; }

    const float* cwp = cw + ph * 2048;
    for (int c = 0; c < 32; c++) {
        const float* qc = qs + c * 190;
        const float v00 = qc[jyA * 19 + jxA];
        const float v01 = qc[jyA * 19 + jxA + 1];
        const float v02 = qc[jyA * 19 + jxA + 2];
        const float v10 = qc[(jyA + 1) * 19 + jxA];
        const float v11 = qc[(jyA + 1) * 19 + jxA + 1];
        const float v12 = qc[(jyA + 1) * 19 + jxA + 2];
        const ull p00 = pk2(v00, v00), p01 = pk2(v01, v01), p02 = pk2(v02, v02);
        const ull p10 = pk2(v10, v10), p11 = pk2(v11, v11), p12 = pk2(v12, v12);
        const ull sa[4] = { p00, p01, p10, p11 };
        const ull sb[4] = { p01, p02, p11, p12 };
        #pragma unroll
        for (int tap = 0; tap < 4; tap++) {
            const ull* wr = (const ull*)(cwp + (tap * 32 + c) * 16);
            #pragma unroll
            for (int p = 0; p < 8; p++) {
                const ull wv = wr[p];
                A[p] = fma2(wv, sa[tap], A[p]);
                B[p] = fma2(wv, sb[tap], B[p]);
            }
        }
    }

    const int oxA = ox0 + 2 * uxA + dx, oyA = oy0 + 2 * uyA + dy;
    const int oxB = oxA + 2;
    const ull* bsp = (const ull*)bs;
    #pragma unroll
    for (int p = 0; p < 8; p++) {
        const ull bb = bsp[p];
        float a0, a1, c0, c1;
        upk2(add2(A[p], bb), a0, a1);
        upk2(add2(B[p], bb), c0, c1);
        h3[(((size_t)b * 16 + 2 * p + 0) * 128 + oyA) * 128 + oxA] = gelu_fast(a0);
        h3[(((size_t)b * 16 + 2 * p + 1) * 128 + oyA) * 128 + oxA] = gelu_fast(a1);
        h3[(((size_t)b * 16 + 2 * p + 0) * 128 + oyA) * 128 + oxB] = gelu_fast(c0);
        h3[(((size_t)b * 16 + 2 * p + 1) * 128 + oyA) * 128 + oxB] = gelu_fast(c1);
    }
}

// ---------------------------------------------------------------------------
// K5: upsample2 + conv4 (16->1) + clip, PHASE-DECOMPOSED (image path). (R14)
// ---------------------------------------------------------------------------
__global__ void k5_up_conv4_clip(const float* __restrict__ h3,
                                 const float* __restrict__ w4,
                                 const float* __restrict__ b4,
                                 float* __restrict__ outF) {
    __shared__ float hs[16 * 18 * 18];
    __shared__ float cw5[256];
    __shared__ float wtmp[144];

    const int b   = blockIdx.z;
    const int ox0 = blockIdx.x * 32, oy0 = blockIdx.y * 32;
    const int t   = threadIdx.x;

    if (t < 144) wtmp[t] = w4[t];
    __syncthreads();

    {
        const int c = t & 15, tap = (t >> 4) & 3, ph = t >> 6;
        const int tx = tap & 1, ty = tap >> 1, dx = ph & 1, dy = ph >> 1;
        const int ys = dy ? (ty ? 2 : 0) : (ty ? 1 : 0);
        const int yc = dy ? (ty ? 1 : 2) : (ty ? 2 : 1);
        const int xs = dx ? (tx ? 2 : 0) : (tx ? 1 : 0);
        const int xc = dx ? (tx ? 1 : 2) : (tx ? 2 : 1);
        float ssum = 0.0f;
        for (int iy = 0; iy < yc; iy++)
            for (int ix = 0; ix < xc; ix++)
                ssum += wtmp[c * 9 + (ys + iy) * 3 + (xs + ix)];
        cw5[t] = ssum;
    }

    const int qyb = (oy0 >> 1) - 1, qxb = (ox0 >> 1) - 1;
    const float* hb = h3 + (size_t)b * 16 * 16384;
    for (int i = t; i < 16 * 324; i += 256) {
        const int c = i / 324, rem = i % 324, r = rem / 18, cc = rem % 18;
        const int gy = qyb + r, gx = qxb + cc;
        float v = 0.0f;
        if (gy >= 0 && gy < 128 && gx >= 0 && gx < 128) v = hb[c * 16384 + gy * 128 + gx];
        hs[c * 324 + r * 18 + cc] = v;
    }
    __syncthreads();

    const int wrp = t >> 5, lane = t & 31;
    const int dx = wrp & 1, dy = (wrp >> 1) & 1, sub = wrp >> 2;
    const float* cwp = cw5 + (dy * 2 + dx) * 64;
    const float bias = b4[0];

    int jx[4], jy[4], ox[4], oy[4];
    #pragma unroll
    for (int i = 0; i < 4; i++) {
        const int idx = sub * 32 + lane + 64 * i;
        const int ux = idx & 15, uy = idx >> 4;
        jx[i] = ux + dx; jy[i] = uy + dy;
        ox[i] = ox0 + 2 * ux + dx; oy[i] = oy0 + 2 * uy + dy;
    }

    float acc[4] = {0.f, 0.f, 0.f, 0.f};
    for (int c = 0; c < 16; c++) {
        const float w00 = cwp[c], w01 = cwp[16 + c], w10 = cwp[32 + c], w11 = cwp[48 + c];
        const float* hc = hs + c * 324;
        #pragma unroll
        for (int i = 0; i < 4; i++) {
            acc[i] = fmaf(hc[jy[i] * 18 + jx[i]],           w00, acc[i]);
            acc[i] = fmaf(hc[jy[i] * 18 + jx[i] + 1],       w01, acc[i]);
            acc[i] = fmaf(hc[(jy[i] + 1) * 18 + jx[i]],     w10, acc[i]);
            acc[i] = fmaf(hc[(jy[i] + 1) * 18 + jx[i] + 1], w11, acc[i]);
        }
    }

    #pragma unroll
    for (int i = 0; i < 4; i++) {
        float a = acc[i] + bias;
        a = fminf(fmaxf(a, -1.0f), 1.0f);
        outF[(size_t)b * 65536 + oy[i] * 256 + ox[i]] = a;
    }
}

// ---------------------------------------------------------------------------
// K6: deterministic final reduction of commit loss (512 partials).
// ---------------------------------------------------------------------------
__global__ void k6_loss(const float* __restrict__ partial, float* __restrict__ outF) {
    __shared__ float red[256];
    const int t = threadIdx.x;
    red[t] = partial[t] + partial[t + 256];
    __syncthreads();
    #pragma unroll
    for (int s2 = 128; s2 > 0; s2 >>= 1) {
        if (t < s2) red[t] += red[t + s2];
        __syncthreads();
    }
    if (t == 0) outF[4194304 + 262144] = red[0] * (1.0f / 8388608.0f);
}

// ---------------------------------------------------------------------------
extern "C" void kernel_launch(void* const* d_in, const int* in_sizes, int n_in,
                              void* d_out, int out_size) {
    const float* x  = (const float*)d_in[0];
    const float* w1 = (const float*)d_in[1];
    const float* b1 = (const float*)d_in[2];
    const float* w2 = (const float*)d_in[3];
    const float* b2 = (const float*)d_in[4];
    const float* cb = (const float*)d_in[5];
    const float* w3 = (const float*)d_in[6];
    const float* b3 = (const float*)d_in[7];
    const float* w4 = (const float*)d_in[8];
    const float* b4 = (const float*)d_in[9];
    float* outF = (float*)d_out;

    float *h1, *h2, *q, *h3, *partial;
    cudaGetSymbolAddress((void**)&h1, g_h1);
    cudaGetSymbolAddress((void**)&h2, g_h2);
    cudaGetSymbolAddress((void**)&q,  g_q);
    cudaGetSymbolAddress((void**)&h3, g_h3);
    cudaGetSymbolAddress((void**)&partial, g_partial);

    cudaFuncSetAttribute(k3_vq,            cudaFuncAttributeMaxDynamicSharedMemorySize, 67584);
    cudaFuncSetAttribute(k4_up_conv3_gelu, cudaFuncAttributeMaxDynamicSharedMemorySize, 57152);

    k1_conv1_pool_gelu<<<dim3(8, 8, BATCH), dim3(16, 16)>>>(x, w1, b1, h1);
    k2_conv2_pool<<<dim3(8, 8, BATCH), 256>>>(h1, w2, b2, h2);
    k3_vq<<<512, 256, 67584>>>(h2, cb, q, outF, partial);
    k4_up_conv3_gelu<<<dim3(4, 8, BATCH), 256, 57152>>>(q, w3, b3, h3);
    k5_up_conv4_clip<<<dim3(8, 8, BATCH), 256>>>(h3, w4, b4, outF);
    k6_loss<<<1, 256>>>(partial, outF);
}